// round 11
// baseline (speedup 1.0000x reference)
#include <cuda_runtime.h>
#include <cuda_bf16.h>
#include <cuda_fp16.h>
#include <math.h>
#include <stdint.h>

#define N_TOK        8192
#define DMODEL       1024
#define DQUERY       256
#define NHEADS       4
#define NSUB         128
#define TOPK         8
#define DLATENT      256
#define DHIDDEN      512
#define NEXPERTS     16384
#define NEG_INF      (-1.0e38f)

// ---------------- scratch (device globals; no allocation allowed) ----------------
__device__ float g_q[N_TOK * DMODEL];
__device__ float g_s1[N_TOK * NHEADS * NSUB];
__device__ float g_s2[N_TOK * NHEADS * NSUB];
__device__ float g_scale[DMODEL];
__device__ float g_shift[DMODEL];
__device__ float g_bnpart[16 * DMODEL];
__device__ float g_Hall[NEXPERTS * DHIDDEN];
__device__ float g_xproj[N_TOK * DHIDDEN];
__device__ float g_acc[N_TOK * DHIDDEN];
__device__ float g_probs[N_TOK * NHEADS * TOPK];
__device__ int   g_eidx[N_TOK * NHEADS * TOPK];
__device__ float g_W1T[DHIDDEN * DLATENT];     // 512 x 256
__device__ float g_WvT[DMODEL * DHIDDEN];      // 1024 x 512

__device__ __forceinline__ float gelu_exact(float x) {
    return 0.5f * x * (1.0f + erff(x * 0.70710678118654752f));
}

__device__ __forceinline__ uint32_t smem_u32(const void* p) {
    uint32_t a;
    asm("{ .reg .u64 t; cvta.to.shared.u64 t, %1; cvt.u32.u64 %0, t; }" : "=r"(a) : "l"(p));
    return a;
}
__device__ __forceinline__ uint32_t sw128(uint32_t o) { return o ^ ((o >> 3) & 0x70); }

__device__ __forceinline__ void ldsm_x4(uint32_t* r, uint32_t addr) {
    asm volatile("ldmatrix.sync.aligned.m8n8.x4.shared.b16 {%0,%1,%2,%3}, [%4];"
                 : "=r"(r[0]), "=r"(r[1]), "=r"(r[2]), "=r"(r[3]) : "r"(addr));
}

// global chunk stage: 128 rows x 64 fp32 -> 8 float4 regs per thread
__device__ __forceinline__ void ch_ldg(const float* __restrict__ src, int ld,
                                       float4* r, int tid)
{
    const int r0 = tid >> 4;
    const int c  = (tid & 15) << 2;
#pragma unroll
    for (int p = 0; p < 8; p++)
        r[p] = *reinterpret_cast<const float4*>(src + (size_t)(r0 + (p << 4)) * ld + c);
}

__device__ __forceinline__ void mma16816h(float* d, const uint32_t* a, const uint32_t* b) {
    asm volatile(
        "mma.sync.aligned.m16n8k16.row.col.f32.f16.f16.f32 "
        "{%0,%1,%2,%3}, {%4,%5,%6,%7}, {%8,%9}, {%0,%1,%2,%3};"
        : "+f"(d[0]), "+f"(d[1]), "+f"(d[2]), "+f"(d[3])
        : "r"(a[0]), "r"(a[1]), "r"(a[2]), "r"(a[3]), "r"(b[0]), "r"(b[1]));
}

#define TILE_BYTES 16384
#define STAGE4_BYTES (4 * TILE_BYTES)
#define GEMM4_SMEM  (2 * STAGE4_BYTES + 1024)
#define STAGE2_BYTES (3 * TILE_BYTES)
#define GEMM2_SMEM  (2 * STAGE2_BYTES + 1024)

// split fp32 -> fp16 hi/lo, two swizzled tiles
__device__ __forceinline__ void hp_cvt_sts2(const float4* r,
                                            char* __restrict__ sm_hi,
                                            char* __restrict__ sm_lo, int tid)
{
    const int r0 = tid >> 4;
    const int c  = (tid & 15) << 2;
#pragma unroll
    for (int p = 0; p < 8; p++) {
        const int row = r0 + (p << 4);
        const float4 v = r[p];
        __half h0 = __float2half_rn(v.x);
        __half h1 = __float2half_rn(v.y);
        __half h2 = __float2half_rn(v.z);
        __half h3 = __float2half_rn(v.w);
        __half l0 = __float2half_rn(v.x - __half2float(h0));
        __half l1 = __float2half_rn(v.y - __half2float(h1));
        __half l2 = __float2half_rn(v.z - __half2float(h2));
        __half l3 = __float2half_rn(v.w - __half2float(h3));
        uint32_t hi01 = ((uint32_t)__half_as_ushort(h1) << 16) | __half_as_ushort(h0);
        uint32_t hi23 = ((uint32_t)__half_as_ushort(h3) << 16) | __half_as_ushort(h2);
        uint32_t lo01 = ((uint32_t)__half_as_ushort(l1) << 16) | __half_as_ushort(l0);
        uint32_t lo23 = ((uint32_t)__half_as_ushort(l3) << 16) | __half_as_ushort(l2);
        const uint32_t off = sw128((uint32_t)(row * 128 + (c << 1)));
        *reinterpret_cast<uint2*>(sm_hi + off) = make_uint2(hi01, hi23);
        *reinterpret_cast<uint2*>(sm_lo + off) = make_uint2(lo01, lo23);
    }
}

// round fp32 -> fp16, single swizzled tile
__device__ __forceinline__ void hp_cvt_sts1(const float4* r,
                                            char* __restrict__ sm_hi, int tid)
{
    const int r0 = tid >> 4;
    const int c  = (tid & 15) << 2;
#pragma unroll
    for (int p = 0; p < 8; p++) {
        const int row = r0 + (p << 4);
        const float4 v = r[p];
        uint32_t hi01 = ((uint32_t)__half_as_ushort(__float2half_rn(v.y)) << 16)
                      | __half_as_ushort(__float2half_rn(v.x));
        uint32_t hi23 = ((uint32_t)__half_as_ushort(__float2half_rn(v.w)) << 16)
                      | __half_as_ushort(__float2half_rn(v.z));
        const uint32_t off = sw128((uint32_t)(row * 128 + (c << 1)));
        *reinterpret_cast<uint2*>(sm_hi + off) = make_uint2(hi01, hi23);
    }
}

// ================================================================
// fp16x4 HMMA GEMM (scoring path) — optional fused normalize on A
// C = A*B^T + bias ; A: MxK fp32 (lda), B: NxK fp32 (ldb); K%64==0
// FUSE: A element (row,k) scaled by nsc/nsh at column
//       ((row&3)*256 + koff + k)   [head-local batchnorm affine]
// ================================================================
template<int FUSE>
__global__ void __launch_bounds__(256, 1)
fp16_gemm(const float* __restrict__ A, int lda,
          const float* __restrict__ B, int ldb,
          float* __restrict__ C, int ldc, int K,
          const float* __restrict__ bias,
          const float* __restrict__ nsc, const float* __restrict__ nsh, int koff)
{
    extern __shared__ char dsm[];
    const uint32_t raw = smem_u32(dsm);
    const uint32_t base = (raw + 1023) & ~1023u;
    char* tiles = dsm + (base - raw);

    const int tid  = threadIdx.x;
    const int lane = tid & 31;
    const int wid  = tid >> 5;
    const int wm = wid & 3;
    const int wn = wid >> 2;
    const int bm = blockIdx.y * 128;
    const int bn = blockIdx.x * 128;

    const float* Ap = A + (size_t)bm * lda;
    const float* Bp = B + (size_t)bn * ldb;
    const int nk = K >> 6;

    // fused-normalize indexing: head is constant per thread
    const int scbase = FUSE ? (((tid >> 4) & 3) * 256 + koff + ((tid & 15) << 2)) : 0;

    float4 ra[8], rb[8];
    ch_ldg(Ap, lda, ra, tid);
    ch_ldg(Bp, ldb, rb, tid);
    if (FUSE) {
        float4 sc4 = *reinterpret_cast<const float4*>(nsc + scbase);
        float4 sh4 = *reinterpret_cast<const float4*>(nsh + scbase);
#pragma unroll
        for (int p = 0; p < 8; p++) {
            ra[p].x = fmaf(ra[p].x, sc4.x, sh4.x);
            ra[p].y = fmaf(ra[p].y, sc4.y, sh4.y);
            ra[p].z = fmaf(ra[p].z, sc4.z, sh4.z);
            ra[p].w = fmaf(ra[p].w, sc4.w, sh4.w);
        }
    }
    hp_cvt_sts2(ra, tiles, tiles + TILE_BYTES, tid);
    hp_cvt_sts2(rb, tiles + 2 * TILE_BYTES, tiles + 3 * TILE_BYTES, tid);
    __syncthreads();

    float acc[2][8][4];
#pragma unroll
    for (int i = 0; i < 2; i++)
#pragma unroll
        for (int j = 0; j < 8; j++)
#pragma unroll
            for (int t = 0; t < 4; t++) acc[i][j][t] = 0.f;

    const int a_row = wm * 32 + (lane & 15);
    const int a_kb0 = (lane >> 4) << 4;
    const int b_row0 = wn * 64 + (lane & 7) + ((lane >> 4) << 3);
    const int b_kb0 = ((lane >> 3) & 1) << 4;

    for (int kc = 0; kc < nk; kc++) {
        const int cur = kc & 1;
        const bool more = (kc + 1 < nk);
        if (more) {
            ch_ldg(Ap + (kc + 1) * 64, lda, ra, tid);
            ch_ldg(Bp + (kc + 1) * 64, ldb, rb, tid);
            if (FUSE) {
                float4 sc4 = *reinterpret_cast<const float4*>(nsc + scbase + (kc + 1) * 64);
                float4 sh4 = *reinterpret_cast<const float4*>(nsh + scbase + (kc + 1) * 64);
#pragma unroll
                for (int p = 0; p < 8; p++) {
                    ra[p].x = fmaf(ra[p].x, sc4.x, sh4.x);
                    ra[p].y = fmaf(ra[p].y, sc4.y, sh4.y);
                    ra[p].z = fmaf(ra[p].z, sc4.z, sh4.z);
                    ra[p].w = fmaf(ra[p].w, sc4.w, sh4.w);
                }
            }
        }
        const uint32_t sb = base + cur * STAGE4_BYTES;
#pragma unroll
        for (int ks = 0; ks < 4; ks++) {
            uint32_t Ah[2][4], Al[2][4];
#pragma unroll
            for (int mf = 0; mf < 2; mf++) {
                uint32_t off = sw128((uint32_t)((a_row + mf * 16) * 128 + ks * 32 + a_kb0));
                ldsm_x4(Ah[mf], sb + off);
                ldsm_x4(Al[mf], sb + TILE_BYTES + off);
            }
            uint32_t Bh[4][4], Bl[4][4];
#pragma unroll
            for (int nf2 = 0; nf2 < 4; nf2++) {
                uint32_t off = sw128((uint32_t)((b_row0 + nf2 * 16) * 128 + ks * 32 + b_kb0));
                ldsm_x4(Bh[nf2], sb + 2 * TILE_BYTES + off);
                ldsm_x4(Bl[nf2], sb + 3 * TILE_BYTES + off);
            }
            // per-accumulator order: AhBh, AlBh, AhBl, AlBl
#pragma unroll
            for (int nf2 = 0; nf2 < 4; nf2++)
#pragma unroll
                for (int mf = 0; mf < 2; mf++) {
                    mma16816h(acc[mf][nf2 * 2 + 0], Ah[mf], Bh[nf2] + 0);
                    mma16816h(acc[mf][nf2 * 2 + 1], Ah[mf], Bh[nf2] + 2);
                }
#pragma unroll
            for (int nf2 = 0; nf2 < 4; nf2++)
#pragma unroll
                for (int mf = 0; mf < 2; mf++) {
                    mma16816h(acc[mf][nf2 * 2 + 0], Al[mf], Bh[nf2] + 0);
                    mma16816h(acc[mf][nf2 * 2 + 1], Al[mf], Bh[nf2] + 2);
                }
#pragma unroll
            for (int nf2 = 0; nf2 < 4; nf2++)
#pragma unroll
                for (int mf = 0; mf < 2; mf++) {
                    mma16816h(acc[mf][nf2 * 2 + 0], Ah[mf], Bl[nf2] + 0);
                    mma16816h(acc[mf][nf2 * 2 + 1], Ah[mf], Bl[nf2] + 2);
                }
#pragma unroll
            for (int nf2 = 0; nf2 < 4; nf2++)
#pragma unroll
                for (int mf = 0; mf < 2; mf++) {
                    mma16816h(acc[mf][nf2 * 2 + 0], Al[mf], Bl[nf2] + 0);
                    mma16816h(acc[mf][nf2 * 2 + 1], Al[mf], Bl[nf2] + 2);
                }
        }
        if (more) {
            char* st = tiles + (cur ^ 1) * STAGE4_BYTES;
            hp_cvt_sts2(ra, st, st + TILE_BYTES, tid);
            hp_cvt_sts2(rb, st + 2 * TILE_BYTES, st + 3 * TILE_BYTES, tid);
        }
        __syncthreads();
    }

#pragma unroll
    for (int mf = 0; mf < 2; mf++) {
        const int row = bm + wm * 32 + mf * 16 + (lane >> 2);
#pragma unroll
        for (int nf = 0; nf < 8; nf++) {
            const int col = bn + wn * 64 + nf * 8 + (lane & 3) * 2;
            float b0 = 0.f, b1 = 0.f;
            if (bias) { b0 = bias[col]; b1 = bias[col + 1]; }
            *reinterpret_cast<float2*>(C + (size_t)row * ldc + col) =
                make_float2(acc[mf][nf][0] + b0, acc[mf][nf][1] + b1);
            *reinterpret_cast<float2*>(C + (size_t)(row + 8) * ldc + col) =
                make_float2(acc[mf][nf][2] + b0, acc[mf][nf][3] + b1);
        }
    }
}

// ================================================================
// fp16x2 HMMA GEMM (continuous GEMMs): A split hi/lo, B rounded
// per-accumulator order: AhBh, AlBh
// ================================================================
template<int ACT>   // 0 = none, 1 = gelu
__global__ void __launch_bounds__(256, 1)
hp2_gemm(const float* __restrict__ A, int lda,
         const float* __restrict__ B, int ldb,
         float* __restrict__ C, int ldc, int K,
         const float* __restrict__ bias, float scale)
{
    extern __shared__ char dsm[];
    const uint32_t raw = smem_u32(dsm);
    const uint32_t base = (raw + 1023) & ~1023u;
    char* tiles = dsm + (base - raw);

    const int tid  = threadIdx.x;
    const int lane = tid & 31;
    const int wid  = tid >> 5;
    const int wm = wid & 3;
    const int wn = wid >> 2;
    const int bm = blockIdx.y * 128;
    const int bn = blockIdx.x * 128;

    const float* Ap = A + (size_t)bm * lda;
    const float* Bp = B + (size_t)bn * ldb;
    const int nk = K >> 6;

    float4 ra[8], rb[8];
    ch_ldg(Ap, lda, ra, tid);
    ch_ldg(Bp, ldb, rb, tid);
    hp_cvt_sts2(ra, tiles, tiles + TILE_BYTES, tid);
    hp_cvt_sts1(rb, tiles + 2 * TILE_BYTES, tid);
    __syncthreads();

    float acc[2][8][4];
#pragma unroll
    for (int i = 0; i < 2; i++)
#pragma unroll
        for (int j = 0; j < 8; j++)
#pragma unroll
            for (int t = 0; t < 4; t++) acc[i][j][t] = 0.f;

    const int a_row = wm * 32 + (lane & 15);
    const int a_kb0 = (lane >> 4) << 4;
    const int b_row0 = wn * 64 + (lane & 7) + ((lane >> 4) << 3);
    const int b_kb0 = ((lane >> 3) & 1) << 4;

    for (int kc = 0; kc < nk; kc++) {
        const int cur = kc & 1;
        const bool more = (kc + 1 < nk);
        if (more) {
            ch_ldg(Ap + (kc + 1) * 64, lda, ra, tid);
            ch_ldg(Bp + (kc + 1) * 64, ldb, rb, tid);
        }
        const uint32_t sb = base + cur * STAGE2_BYTES;
#pragma unroll
        for (int ks = 0; ks < 4; ks++) {
            uint32_t Ah[2][4], Al[2][4];
#pragma unroll
            for (int mf = 0; mf < 2; mf++) {
                uint32_t off = sw128((uint32_t)((a_row + mf * 16) * 128 + ks * 32 + a_kb0));
                ldsm_x4(Ah[mf], sb + off);
                ldsm_x4(Al[mf], sb + TILE_BYTES + off);
            }
            uint32_t Bh[4][4];
#pragma unroll
            for (int nf2 = 0; nf2 < 4; nf2++) {
                uint32_t off = sw128((uint32_t)((b_row0 + nf2 * 16) * 128 + ks * 32 + b_kb0));
                ldsm_x4(Bh[nf2], sb + 2 * TILE_BYTES + off);
            }
#pragma unroll
            for (int nf2 = 0; nf2 < 4; nf2++)
#pragma unroll
                for (int mf = 0; mf < 2; mf++) {
                    mma16816h(acc[mf][nf2 * 2 + 0], Ah[mf], Bh[nf2] + 0);
                    mma16816h(acc[mf][nf2 * 2 + 1], Ah[mf], Bh[nf2] + 2);
                }
#pragma unroll
            for (int nf2 = 0; nf2 < 4; nf2++)
#pragma unroll
                for (int mf = 0; mf < 2; mf++) {
                    mma16816h(acc[mf][nf2 * 2 + 0], Al[mf], Bh[nf2] + 0);
                    mma16816h(acc[mf][nf2 * 2 + 1], Al[mf], Bh[nf2] + 2);
                }
        }
        if (more) {
            char* st = tiles + (cur ^ 1) * STAGE2_BYTES;
            hp_cvt_sts2(ra, st, st + TILE_BYTES, tid);
            hp_cvt_sts1(rb, st + 2 * TILE_BYTES, tid);
        }
        __syncthreads();
    }

#pragma unroll
    for (int mf = 0; mf < 2; mf++) {
        const int row = bm + wm * 32 + mf * 16 + (lane >> 2);
#pragma unroll
        for (int nf = 0; nf < 8; nf++) {
            const int col = bn + wn * 64 + nf * 8 + (lane & 3) * 2;
            float b0 = 0.f, b1 = 0.f;
            if (bias) { b0 = bias[col]; b1 = bias[col + 1]; }
            float v0 = acc[mf][nf][0] + b0;
            float v1 = acc[mf][nf][1] + b1;
            float v2 = acc[mf][nf][2] + b0;
            float v3 = acc[mf][nf][3] + b1;
            if (ACT == 1) {
                v0 = gelu_exact(v0); v1 = gelu_exact(v1);
                v2 = gelu_exact(v2); v3 = gelu_exact(v3);
            }
            v0 *= scale; v1 *= scale; v2 *= scale; v3 *= scale;
            *reinterpret_cast<float2*>(C + (size_t)row * ldc + col) = make_float2(v0, v1);
            *reinterpret_cast<float2*>(C + (size_t)(row + 8) * ldc + col) = make_float2(v2, v3);
        }
    }
}

// ---------------- transpose ----------------
__global__ void __launch_bounds__(256)
transpose_kernel(const float* __restrict__ src, int sld, int rows,
                 float* __restrict__ dst)
{
    __shared__ float t[32][33];
    const int bx = blockIdx.x * 32, by = blockIdx.y * 32;
    int x = bx + threadIdx.x, y = by + threadIdx.y;
#pragma unroll
    for (int i = 0; i < 32; i += 8)
        t[threadIdx.y + i][threadIdx.x] = src[(size_t)(y + i) * sld + x];
    __syncthreads();
    x = by + threadIdx.x; y = bx + threadIdx.y;
#pragma unroll
    for (int i = 0; i < 32; i += 8)
        dst[(size_t)(y + i) * rows + x] = t[threadIdx.x][threadIdx.y + i];
}

// ---------------- batchnorm: partial stats, then finalize ----------------
__global__ void __launch_bounds__(256)
bn_part_kernel(const float* __restrict__ q, float* __restrict__ part)
{
    const int lane32 = threadIdx.x & 31;
    const int grp = threadIdx.x >> 5;
    const int col = blockIdx.x * 32 + lane32;
    const int slice = blockIdx.y;
    const int r0 = slice * (N_TOK / 8);
    float s = 0.f, ss = 0.f;
    for (int r = grp; r < N_TOK / 8; r += 8) {
        float v = q[(size_t)(r0 + r) * DMODEL + col];
        s += v;
        ss += v * v;
    }
    __shared__ float sh_s[8][33], sh_q[8][33];
    sh_s[grp][lane32] = s;
    sh_q[grp][lane32] = ss;
    __syncthreads();
    if (grp == 0) {
        float ts = 0.f, tss = 0.f;
#pragma unroll
        for (int i = 0; i < 8; i++) { ts += sh_s[i][lane32]; tss += sh_q[i][lane32]; }
        part[(2 * slice + 0) * DMODEL + col] = ts;
        part[(2 * slice + 1) * DMODEL + col] = tss;
    }
}

__global__ void __launch_bounds__(256)
bn_final_kernel(const float* __restrict__ part,
                const float* __restrict__ gamma, const float* __restrict__ beta,
                float* __restrict__ scale, float* __restrict__ shift)
{
    const int col = blockIdx.x * 256 + threadIdx.x;
    float s = 0.f, ss = 0.f;
#pragma unroll
    for (int i = 0; i < 8; i++) {
        s  += part[(2 * i + 0) * DMODEL + col];
        ss += part[(2 * i + 1) * DMODEL + col];
    }
    float mean = s * (1.0f / N_TOK);
    float var = ss * (1.0f / N_TOK) - mean * mean;
    float rstd = rsqrtf(var + 1e-5f);
    float sc = gamma[col] * rstd;
    scale[col] = sc;
    shift[col] = beta[col] - mean * sc;
}

// ---------------- warp-collective top-16 of 128 values ----------------
__device__ __forceinline__ void warp_top16(const float* __restrict__ row,
                                           float* __restrict__ ov, int* __restrict__ oi,
                                           int lane)
{
    float v0 = row[lane], v1 = row[lane + 32], v2 = row[lane + 64], v3 = row[lane + 96];
#pragma unroll 1
    for (int it = 0; it < 16; it++) {
        float bv = v0; int bu = 0;
        if (v1 > bv) { bv = v1; bu = 1; }
        if (v2 > bv) { bv = v2; bu = 2; }
        if (v3 > bv) { bv = v3; bu = 3; }
        int bidx = lane + (bu << 5);
#pragma unroll
        for (int off = 16; off; off >>= 1) {
            float ovv = __shfl_down_sync(0xffffffffu, bv, off);
            int oii = __shfl_down_sync(0xffffffffu, bidx, off);
            if (ovv > bv) { bv = ovv; bidx = oii; }
        }
        bv = __shfl_sync(0xffffffffu, bv, 0);
        bidx = __shfl_sync(0xffffffffu, bidx, 0);
        if (lane == 0) { ov[it] = bv; oi[it] = bidx; }
        if ((bidx & 31) == lane) {
            int u = bidx >> 5;
            if (u == 0) v0 = NEG_INF;
            else if (u == 1) v1 = NEG_INF;
            else if (u == 2) v2 = NEG_INF;
            else v3 = NEG_INF;
        }
    }
}

__global__ void __launch_bounds__(256)
topk_kernel(const float* __restrict__ s1, const float* __restrict__ s2,
            float* __restrict__ probs, int* __restrict__ eidx)
{
    const int wid = threadIdx.x >> 5;
    const int lane = threadIdx.x & 31;
    const int row = blockIdx.x * 8 + wid;
    __shared__ float tv1[8][16], tv2[8][16];
    __shared__ int ti1[8][16], ti2[8][16];

    warp_top16(s1 + (size_t)row * NSUB, tv1[wid], ti1[wid], lane);
    warp_top16(s2 + (size_t)row * NSUB, tv2[wid], ti2[wid], lane);
    __syncwarp();

    float cv[8];
#pragma unroll
    for (int t = 0; t < 8; t++) {
        int c = lane * 8 + t;
        cv[t] = tv1[wid][c >> 4] + tv2[wid][c & 15];
    }
    float fv[8]; int fi[8];
#pragma unroll 1
    for (int it = 0; it < 8; it++) {
        float bv = cv[0]; int bt = 0;
#pragma unroll
        for (int t = 1; t < 8; t++) if (cv[t] > bv) { bv = cv[t]; bt = t; }
        int bidx = lane * 8 + bt;
#pragma unroll
        for (int off = 16; off; off >>= 1) {
            float ovv = __shfl_down_sync(0xffffffffu, bv, off);
            int oii = __shfl_down_sync(0xffffffffu, bidx, off);
            if (ovv > bv) { bv = ovv; bidx = oii; }
        }
        bv = __shfl_sync(0xffffffffu, bv, 0);
        bidx = __shfl_sync(0xffffffffu, bidx, 0);
        fv[it] = bv; fi[it] = bidx;
        if ((bidx >> 3) == lane) cv[bidx & 7] = NEG_INF;
    }

    if (lane < 8) {
        float m = fv[0];
        float sum = 0.f;
#pragma unroll
        for (int i = 0; i < 8; i++) sum += expf(fv[i] - m);
        float p = expf(fv[lane] - m) / sum;
        int c = fi[lane];
        int i1 = ti1[wid][c >> 4];
        int i2 = ti2[wid][c & 15];
        probs[(size_t)row * 8 + lane] = p;
        eidx[(size_t)row * 8 + lane] = i1 * NSUB + i2;
    }
}

// ---------------- MoE per-token: warp-per-expert, sync-free mainloop ----------------
__global__ void __launch_bounds__(256)
moe_kernel(const float* __restrict__ xproj, const float* __restrict__ Hall,
           const float* __restrict__ probs, const int* __restrict__ eidx,
           float* __restrict__ accb)
{
    const int n = blockIdx.x;
    const int t = threadIdx.x;
    const int lane = t & 31, w = t >> 5;
    __shared__ float part[8][DHIDDEN];

    float xpr[16];
#pragma unroll
    for (int j = 0; j < 16; j++)
        xpr[j] = xproj[(size_t)n * DHIDDEN + j * 32 + lane];

    float pa[16];
#pragma unroll
    for (int j = 0; j < 16; j++) pa[j] = 0.f;

#pragma unroll
    for (int je = 0; je < 4; je++) {
        const int s = w * 4 + je;
        const int e = eidx[n * 32 + s];
        const float* H = Hall + (size_t)e * DHIDDEN;
        float h[16];
#pragma unroll
        for (int j = 0; j < 16; j++) h[j] = H[j * 32 + lane];
        float dot = 0.f;
#pragma unroll
        for (int j = 0; j < 16; j++) dot = fmaf(xpr[j], h[j], dot);
#pragma unroll
        for (int off = 16; off; off >>= 1)
            dot += __shfl_xor_sync(0xffffffffu, dot, off);
        const float act = gelu_exact(dot) * probs[n * 32 + s];
#pragma unroll
        for (int j = 0; j < 16; j++) pa[j] = fmaf(act, h[j], pa[j]);
    }
#pragma unroll
    for (int j = 0; j < 16; j++) part[w][j * 32 + lane] = pa[j];
    __syncthreads();

    float a0 = 0.f, a1 = 0.f;
#pragma unroll
    for (int w2 = 0; w2 < 8; w2++) {
        a0 += part[w2][t];
        a1 += part[w2][t + 256];
    }
    accb[(size_t)n * DHIDDEN + t] = a0;
    accb[(size_t)n * DHIDDEN + 256 + t] = a1;
}

// ---------------- host launch ----------------
extern "C" void kernel_launch(void* const* d_in, const int* in_sizes, int n_in,
                              void* d_out, int out_size)
{
    const float* x       = (const float*)d_in[0];
    const float* Wq      = (const float*)d_in[1];
    const float* bq      = (const float*)d_in[2];
    const float* gamma   = (const float*)d_in[3];
    const float* beta    = (const float*)d_in[4];
    const float* sk1     = (const float*)d_in[5];
    const float* sk2     = (const float*)d_in[6];
    const float* latents = (const float*)d_in[7];
    const float* W1      = (const float*)d_in[8];
    const float* W2      = (const float*)d_in[9];
    float* out = (float*)d_out;

    void *pq, *ps1, *ps2, *psc, *psh, *pbp, *pH, *pxp, *pacc, *ppr, *pei, *pw1t, *pwvt;
    cudaGetSymbolAddress(&pq, g_q);
    cudaGetSymbolAddress(&ps1, g_s1);
    cudaGetSymbolAddress(&ps2, g_s2);
    cudaGetSymbolAddress(&psc, g_scale);
    cudaGetSymbolAddress(&psh, g_shift);
    cudaGetSymbolAddress(&pbp, g_bnpart);
    cudaGetSymbolAddress(&pH, g_Hall);
    cudaGetSymbolAddress(&pxp, g_xproj);
    cudaGetSymbolAddress(&pacc, g_acc);
    cudaGetSymbolAddress(&ppr, g_probs);
    cudaGetSymbolAddress(&pei, g_eidx);
    cudaGetSymbolAddress(&pw1t, g_W1T);
    cudaGetSymbolAddress(&pwvt, g_WvT);

    float* q_buf   = (float*)pq;
    float* s1_buf  = (float*)ps1;
    float* s2_buf  = (float*)ps2;
    float* sc_buf  = (float*)psc;
    float* sh_buf  = (float*)psh;
    float* bp_buf  = (float*)pbp;
    float* H_buf   = (float*)pH;
    float* xp_buf  = (float*)pxp;
    float* acc_buf = (float*)pacc;
    float* pr_buf  = (float*)ppr;
    int*   ei_buf  = (int*)pei;
    float* w1t_buf = (float*)pw1t;
    float* wvt_buf = (float*)pwvt;

    cudaFuncSetAttribute(fp16_gemm<0>, cudaFuncAttributeMaxDynamicSharedMemorySize, GEMM4_SMEM);
    cudaFuncSetAttribute(fp16_gemm<1>, cudaFuncAttributeMaxDynamicSharedMemorySize, GEMM4_SMEM);
    cudaFuncSetAttribute(hp2_gemm<0>, cudaFuncAttributeMaxDynamicSharedMemorySize, GEMM2_SMEM);
    cudaFuncSetAttribute(hp2_gemm<1>, cudaFuncAttributeMaxDynamicSharedMemorySize, GEMM2_SMEM);

    const dim3 blk(256);
    const dim3 tblk(32, 8);

    transpose_kernel<<<dim3(DHIDDEN / 32, DLATENT / 32), tblk>>>(W1, DHIDDEN, DLATENT, w1t_buf);
    transpose_kernel<<<dim3(DMODEL / 32, DHIDDEN / 32), tblk>>>(W2 + DMODEL, 2 * DMODEL, DHIDDEN, wvt_buf);

    // 1) q = x @ Wq^T + bq   (fp16x4)
    fp16_gemm<0><<<dim3(DMODEL / 128, N_TOK / 128), blk, GEMM4_SMEM>>>(
        x, DMODEL, Wq, DMODEL, q_buf, DMODEL, DMODEL, bq, nullptr, nullptr, 0);

    // 2) batchnorm stats
    bn_part_kernel<<<dim3(DMODEL / 32, 8), blk>>>(q_buf, bp_buf);
    bn_final_kernel<<<DMODEL / 256, blk>>>(bp_buf, gamma, beta, sc_buf, sh_buf);

    // H_all = gelu(latents @ W1T^T)   (fp16x2, independent of scoring chain)
    hp2_gemm<1><<<dim3(DHIDDEN / 128, NEXPERTS / 128), blk, GEMM2_SMEM>>>(
        latents, DLATENT, w1t_buf, DLATENT, H_buf, DHIDDEN, DLATENT, nullptr, 1.0f);

    // 4) s1/s2 (fp16x4, fused batchnorm affine on A)
    fp16_gemm<1><<<dim3(1, (N_TOK * NHEADS) / 128), blk, GEMM4_SMEM>>>(
        q_buf, DQUERY, sk1, NSUB, s1_buf, NSUB, NSUB, nullptr, sc_buf, sh_buf, 0);
    fp16_gemm<1><<<dim3(1, (N_TOK * NHEADS) / 128), blk, GEMM4_SMEM>>>(
        q_buf + 128, DQUERY, sk2, NSUB, s2_buf, NSUB, NSUB, nullptr, sc_buf, sh_buf, 128);

    // 5) two-level top-k
    topk_kernel<<<(N_TOK * NHEADS) / 8, blk>>>(s1_buf, s2_buf, pr_buf, ei_buf);

    // 7) x_proj = x @ W2[:, :D]^T   (fp16x2)
    hp2_gemm<0><<<dim3(DHIDDEN / 128, N_TOK / 128), blk, GEMM2_SMEM>>>(
        x, DMODEL, W2, 2 * DMODEL, xp_buf, DHIDDEN, DMODEL, nullptr, 1.0f);

    // 8) MoE gather / act / accumulate
    moe_kernel<<<N_TOK, blk>>>(xp_buf, H_buf, pr_buf, ei_buf, acc_buf);

    // 9) out = acc @ WvT^T / 4   (fp16x2)
    hp2_gemm<0><<<dim3(DMODEL / 128, N_TOK / 128), blk, GEMM2_SMEM>>>(
        acc_buf, DHIDDEN, wvt_buf, DHIDDEN, out, DMODEL, DHIDDEN, nullptr, 0.25f);
}

// round 12
// speedup vs baseline: 1.5064x; 1.5064x over previous
#include <cuda_runtime.h>
#include <cuda_bf16.h>
#include <cuda_fp16.h>
#include <math.h>
#include <stdint.h>

#define N_TOK        8192
#define DMODEL       1024
#define DQUERY       256
#define NHEADS       4
#define NSUB         128
#define TOPK         8
#define DLATENT      256
#define DHIDDEN      512
#define NEXPERTS     16384
#define NEG_INF      (-1.0e38f)

// ---------------- scratch (device globals; no allocation allowed) ----------------
__device__ float g_q[N_TOK * DMODEL];
__device__ float g_s1[N_TOK * NHEADS * NSUB];
__device__ float g_s2[N_TOK * NHEADS * NSUB];
__device__ float g_scale[DMODEL];
__device__ float g_shift[DMODEL];
__device__ float g_bnpart[16 * DMODEL];
__device__ float g_Hall[NEXPERTS * DHIDDEN];
__device__ float g_xproj[N_TOK * DHIDDEN];
__device__ float g_acc[N_TOK * DHIDDEN];
__device__ float g_probs[N_TOK * NHEADS * TOPK];
__device__ int   g_eidx[N_TOK * NHEADS * TOPK];
__device__ float g_W1T[DHIDDEN * DLATENT];     // 512 x 256
__device__ float g_WvT[DMODEL * DHIDDEN];      // 1024 x 512

__device__ __forceinline__ float gelu_exact(float x) {
    return 0.5f * x * (1.0f + erff(x * 0.70710678118654752f));
}

__device__ __forceinline__ uint32_t smem_u32(const void* p) {
    uint32_t a;
    asm("{ .reg .u64 t; cvta.to.shared.u64 t, %1; cvt.u32.u64 %0, t; }" : "=r"(a) : "l"(p));
    return a;
}
__device__ __forceinline__ uint32_t sw128(uint32_t o) { return o ^ ((o >> 3) & 0x70); }

__device__ __forceinline__ void ldsm_x4(uint32_t* r, uint32_t addr) {
    asm volatile("ldmatrix.sync.aligned.m8n8.x4.shared.b16 {%0,%1,%2,%3}, [%4];"
                 : "=r"(r[0]), "=r"(r[1]), "=r"(r[2]), "=r"(r[3]) : "r"(addr));
}

// global chunk stage: 128 rows x 64 fp32 -> 8 float4 regs per thread
__device__ __forceinline__ void ch_ldg(const float* __restrict__ src, int ld,
                                       float4* r, int tid)
{
    const int r0 = tid >> 4;
    const int c  = (tid & 15) << 2;
#pragma unroll
    for (int p = 0; p < 8; p++)
        r[p] = *reinterpret_cast<const float4*>(src + (size_t)(r0 + (p << 4)) * ld + c);
}

__device__ __forceinline__ void mma16816h(float* d, const uint32_t* a, const uint32_t* b) {
    asm volatile(
        "mma.sync.aligned.m16n8k16.row.col.f32.f16.f16.f32 "
        "{%0,%1,%2,%3}, {%4,%5,%6,%7}, {%8,%9}, {%0,%1,%2,%3};"
        : "+f"(d[0]), "+f"(d[1]), "+f"(d[2]), "+f"(d[3])
        : "r"(a[0]), "r"(a[1]), "r"(a[2]), "r"(a[3]), "r"(b[0]), "r"(b[1]));
}

#define TILE_BYTES 16384
#define STAGE4_BYTES (4 * TILE_BYTES)
#define GEMM4_SMEM  (2 * STAGE4_BYTES + 1024)
#define STAGE2_BYTES (3 * TILE_BYTES)
#define GEMM2_SMEM  (2 * STAGE2_BYTES + 1024)

// split fp32 -> fp16 hi/lo, two swizzled tiles
__device__ __forceinline__ void hp_cvt_sts2(const float4* r,
                                            char* __restrict__ sm_hi,
                                            char* __restrict__ sm_lo, int tid)
{
    const int r0 = tid >> 4;
    const int c  = (tid & 15) << 2;
#pragma unroll
    for (int p = 0; p < 8; p++) {
        const int row = r0 + (p << 4);
        const float4 v = r[p];
        __half h0 = __float2half_rn(v.x);
        __half h1 = __float2half_rn(v.y);
        __half h2 = __float2half_rn(v.z);
        __half h3 = __float2half_rn(v.w);
        __half l0 = __float2half_rn(v.x - __half2float(h0));
        __half l1 = __float2half_rn(v.y - __half2float(h1));
        __half l2 = __float2half_rn(v.z - __half2float(h2));
        __half l3 = __float2half_rn(v.w - __half2float(h3));
        uint32_t hi01 = ((uint32_t)__half_as_ushort(h1) << 16) | __half_as_ushort(h0);
        uint32_t hi23 = ((uint32_t)__half_as_ushort(h3) << 16) | __half_as_ushort(h2);
        uint32_t lo01 = ((uint32_t)__half_as_ushort(l1) << 16) | __half_as_ushort(l0);
        uint32_t lo23 = ((uint32_t)__half_as_ushort(l3) << 16) | __half_as_ushort(l2);
        const uint32_t off = sw128((uint32_t)(row * 128 + (c << 1)));
        *reinterpret_cast<uint2*>(sm_hi + off) = make_uint2(hi01, hi23);
        *reinterpret_cast<uint2*>(sm_lo + off) = make_uint2(lo01, lo23);
    }
}

// round fp32 -> fp16, single swizzled tile
__device__ __forceinline__ void hp_cvt_sts1(const float4* r,
                                            char* __restrict__ sm_hi, int tid)
{
    const int r0 = tid >> 4;
    const int c  = (tid & 15) << 2;
#pragma unroll
    for (int p = 0; p < 8; p++) {
        const int row = r0 + (p << 4);
        const float4 v = r[p];
        uint32_t hi01 = ((uint32_t)__half_as_ushort(__float2half_rn(v.y)) << 16)
                      | __half_as_ushort(__float2half_rn(v.x));
        uint32_t hi23 = ((uint32_t)__half_as_ushort(__float2half_rn(v.w)) << 16)
                      | __half_as_ushort(__float2half_rn(v.z));
        const uint32_t off = sw128((uint32_t)(row * 128 + (c << 1)));
        *reinterpret_cast<uint2*>(sm_hi + off) = make_uint2(hi01, hi23);
    }
}

// ================================================================
// fp16x4 HMMA GEMM (scoring path — near-fp32 accuracy)
// C = A*B^T + bias ; A: MxK fp32 (lda), B: NxK fp32 (ldb); K%64==0
// ================================================================
__global__ void __launch_bounds__(256, 1)
fp16_gemm(const float* __restrict__ A, int lda,
          const float* __restrict__ B, int ldb,
          float* __restrict__ C, int ldc, int K,
          const float* __restrict__ bias)
{
    extern __shared__ char dsm[];
    const uint32_t raw = smem_u32(dsm);
    const uint32_t base = (raw + 1023) & ~1023u;
    char* tiles = dsm + (base - raw);

    const int tid  = threadIdx.x;
    const int lane = tid & 31;
    const int wid  = tid >> 5;
    const int wm = wid & 3;
    const int wn = wid >> 2;
    const int bm = blockIdx.y * 128;
    const int bn = blockIdx.x * 128;

    const float* Ap = A + (size_t)bm * lda;
    const float* Bp = B + (size_t)bn * ldb;
    const int nk = K >> 6;

    float4 ra[8], rb[8];
    ch_ldg(Ap, lda, ra, tid);
    ch_ldg(Bp, ldb, rb, tid);
    hp_cvt_sts2(ra, tiles, tiles + TILE_BYTES, tid);
    hp_cvt_sts2(rb, tiles + 2 * TILE_BYTES, tiles + 3 * TILE_BYTES, tid);
    __syncthreads();

    float acc[2][8][4];
#pragma unroll
    for (int i = 0; i < 2; i++)
#pragma unroll
        for (int j = 0; j < 8; j++)
#pragma unroll
            for (int t = 0; t < 4; t++) acc[i][j][t] = 0.f;

    const int a_row = wm * 32 + (lane & 15);
    const int a_kb0 = (lane >> 4) << 4;
    const int b_row0 = wn * 64 + (lane & 7) + ((lane >> 4) << 3);
    const int b_kb0 = ((lane >> 3) & 1) << 4;

    for (int kc = 0; kc < nk; kc++) {
        const int cur = kc & 1;
        const bool more = (kc + 1 < nk);
        if (more) {
            ch_ldg(Ap + (kc + 1) * 64, lda, ra, tid);
            ch_ldg(Bp + (kc + 1) * 64, ldb, rb, tid);
        }
        const uint32_t sb = base + cur * STAGE4_BYTES;
#pragma unroll
        for (int ks = 0; ks < 4; ks++) {
            uint32_t Ah[2][4], Al[2][4];
#pragma unroll
            for (int mf = 0; mf < 2; mf++) {
                uint32_t off = sw128((uint32_t)((a_row + mf * 16) * 128 + ks * 32 + a_kb0));
                ldsm_x4(Ah[mf], sb + off);
                ldsm_x4(Al[mf], sb + TILE_BYTES + off);
            }
            uint32_t Bh[4][4], Bl[4][4];
#pragma unroll
            for (int nf2 = 0; nf2 < 4; nf2++) {
                uint32_t off = sw128((uint32_t)((b_row0 + nf2 * 16) * 128 + ks * 32 + b_kb0));
                ldsm_x4(Bh[nf2], sb + 2 * TILE_BYTES + off);
                ldsm_x4(Bl[nf2], sb + 3 * TILE_BYTES + off);
            }
            // per-accumulator order: AhBh, AlBh, AhBl, AlBl
#pragma unroll
            for (int nf2 = 0; nf2 < 4; nf2++)
#pragma unroll
                for (int mf = 0; mf < 2; mf++) {
                    mma16816h(acc[mf][nf2 * 2 + 0], Ah[mf], Bh[nf2] + 0);
                    mma16816h(acc[mf][nf2 * 2 + 1], Ah[mf], Bh[nf2] + 2);
                }
#pragma unroll
            for (int nf2 = 0; nf2 < 4; nf2++)
#pragma unroll
                for (int mf = 0; mf < 2; mf++) {
                    mma16816h(acc[mf][nf2 * 2 + 0], Al[mf], Bh[nf2] + 0);
                    mma16816h(acc[mf][nf2 * 2 + 1], Al[mf], Bh[nf2] + 2);
                }
#pragma unroll
            for (int nf2 = 0; nf2 < 4; nf2++)
#pragma unroll
                for (int mf = 0; mf < 2; mf++) {
                    mma16816h(acc[mf][nf2 * 2 + 0], Ah[mf], Bl[nf2] + 0);
                    mma16816h(acc[mf][nf2 * 2 + 1], Ah[mf], Bl[nf2] + 2);
                }
#pragma unroll
            for (int nf2 = 0; nf2 < 4; nf2++)
#pragma unroll
                for (int mf = 0; mf < 2; mf++) {
                    mma16816h(acc[mf][nf2 * 2 + 0], Al[mf], Bl[nf2] + 0);
                    mma16816h(acc[mf][nf2 * 2 + 1], Al[mf], Bl[nf2] + 2);
                }
        }
        if (more) {
            char* st = tiles + (cur ^ 1) * STAGE4_BYTES;
            hp_cvt_sts2(ra, st, st + TILE_BYTES, tid);
            hp_cvt_sts2(rb, st + 2 * TILE_BYTES, st + 3 * TILE_BYTES, tid);
        }
        __syncthreads();
    }

#pragma unroll
    for (int mf = 0; mf < 2; mf++) {
        const int row = bm + wm * 32 + mf * 16 + (lane >> 2);
#pragma unroll
        for (int nf = 0; nf < 8; nf++) {
            const int col = bn + wn * 64 + nf * 8 + (lane & 3) * 2;
            float b0 = 0.f, b1 = 0.f;
            if (bias) { b0 = bias[col]; b1 = bias[col + 1]; }
            *reinterpret_cast<float2*>(C + (size_t)row * ldc + col) =
                make_float2(acc[mf][nf][0] + b0, acc[mf][nf][1] + b1);
            *reinterpret_cast<float2*>(C + (size_t)(row + 8) * ldc + col) =
                make_float2(acc[mf][nf][2] + b0, acc[mf][nf][3] + b1);
        }
    }
}

// ================================================================
// fp16x2 HMMA GEMM (continuous GEMMs): A split hi/lo, B rounded
// per-accumulator order: AhBh, AlBh
// ================================================================
template<int ACT>   // 0 = none, 1 = gelu
__global__ void __launch_bounds__(256, 1)
hp2_gemm(const float* __restrict__ A, int lda,
         const float* __restrict__ B, int ldb,
         float* __restrict__ C, int ldc, int K,
         const float* __restrict__ bias, float scale)
{
    extern __shared__ char dsm[];
    const uint32_t raw = smem_u32(dsm);
    const uint32_t base = (raw + 1023) & ~1023u;
    char* tiles = dsm + (base - raw);

    const int tid  = threadIdx.x;
    const int lane = tid & 31;
    const int wid  = tid >> 5;
    const int wm = wid & 3;
    const int wn = wid >> 2;
    const int bm = blockIdx.y * 128;
    const int bn = blockIdx.x * 128;

    const float* Ap = A + (size_t)bm * lda;
    const float* Bp = B + (size_t)bn * ldb;
    const int nk = K >> 6;

    float4 ra[8], rb[8];
    ch_ldg(Ap, lda, ra, tid);
    ch_ldg(Bp, ldb, rb, tid);
    hp_cvt_sts2(ra, tiles, tiles + TILE_BYTES, tid);
    hp_cvt_sts1(rb, tiles + 2 * TILE_BYTES, tid);
    __syncthreads();

    float acc[2][8][4];
#pragma unroll
    for (int i = 0; i < 2; i++)
#pragma unroll
        for (int j = 0; j < 8; j++)
#pragma unroll
            for (int t = 0; t < 4; t++) acc[i][j][t] = 0.f;

    const int a_row = wm * 32 + (lane & 15);
    const int a_kb0 = (lane >> 4) << 4;
    const int b_row0 = wn * 64 + (lane & 7) + ((lane >> 4) << 3);
    const int b_kb0 = ((lane >> 3) & 1) << 4;

    for (int kc = 0; kc < nk; kc++) {
        const int cur = kc & 1;
        const bool more = (kc + 1 < nk);
        if (more) {
            ch_ldg(Ap + (kc + 1) * 64, lda, ra, tid);
            ch_ldg(Bp + (kc + 1) * 64, ldb, rb, tid);
        }
        const uint32_t sb = base + cur * STAGE2_BYTES;
#pragma unroll
        for (int ks = 0; ks < 4; ks++) {
            uint32_t Ah[2][4], Al[2][4];
#pragma unroll
            for (int mf = 0; mf < 2; mf++) {
                uint32_t off = sw128((uint32_t)((a_row + mf * 16) * 128 + ks * 32 + a_kb0));
                ldsm_x4(Ah[mf], sb + off);
                ldsm_x4(Al[mf], sb + TILE_BYTES + off);
            }
            uint32_t Bh[4][4];
#pragma unroll
            for (int nf2 = 0; nf2 < 4; nf2++) {
                uint32_t off = sw128((uint32_t)((b_row0 + nf2 * 16) * 128 + ks * 32 + b_kb0));
                ldsm_x4(Bh[nf2], sb + 2 * TILE_BYTES + off);
            }
#pragma unroll
            for (int nf2 = 0; nf2 < 4; nf2++)
#pragma unroll
                for (int mf = 0; mf < 2; mf++) {
                    mma16816h(acc[mf][nf2 * 2 + 0], Ah[mf], Bh[nf2] + 0);
                    mma16816h(acc[mf][nf2 * 2 + 1], Ah[mf], Bh[nf2] + 2);
                }
#pragma unroll
            for (int nf2 = 0; nf2 < 4; nf2++)
#pragma unroll
                for (int mf = 0; mf < 2; mf++) {
                    mma16816h(acc[mf][nf2 * 2 + 0], Al[mf], Bh[nf2] + 0);
                    mma16816h(acc[mf][nf2 * 2 + 1], Al[mf], Bh[nf2] + 2);
                }
        }
        if (more) {
            char* st = tiles + (cur ^ 1) * STAGE2_BYTES;
            hp_cvt_sts2(ra, st, st + TILE_BYTES, tid);
            hp_cvt_sts1(rb, st + 2 * TILE_BYTES, tid);
        }
        __syncthreads();
    }

#pragma unroll
    for (int mf = 0; mf < 2; mf++) {
        const int row = bm + wm * 32 + mf * 16 + (lane >> 2);
#pragma unroll
        for (int nf = 0; nf < 8; nf++) {
            const int col = bn + wn * 64 + nf * 8 + (lane & 3) * 2;
            float b0 = 0.f, b1 = 0.f;
            if (bias) { b0 = bias[col]; b1 = bias[col + 1]; }
            float v0 = acc[mf][nf][0] + b0;
            float v1 = acc[mf][nf][1] + b1;
            float v2 = acc[mf][nf][2] + b0;
            float v3 = acc[mf][nf][3] + b1;
            if (ACT == 1) {
                v0 = gelu_exact(v0); v1 = gelu_exact(v1);
                v2 = gelu_exact(v2); v3 = gelu_exact(v3);
            }
            v0 *= scale; v1 *= scale; v2 *= scale; v3 *= scale;
            *reinterpret_cast<float2*>(C + (size_t)row * ldc + col) = make_float2(v0, v1);
            *reinterpret_cast<float2*>(C + (size_t)(row + 8) * ldc + col) = make_float2(v2, v3);
        }
    }
}

// ---------------- transpose ----------------
__global__ void __launch_bounds__(256)
transpose_kernel(const float* __restrict__ src, int sld, int rows,
                 float* __restrict__ dst)
{
    __shared__ float t[32][33];
    const int bx = blockIdx.x * 32, by = blockIdx.y * 32;
    int x = bx + threadIdx.x, y = by + threadIdx.y;
#pragma unroll
    for (int i = 0; i < 32; i += 8)
        t[threadIdx.y + i][threadIdx.x] = src[(size_t)(y + i) * sld + x];
    __syncthreads();
    x = by + threadIdx.x; y = bx + threadIdx.y;
#pragma unroll
    for (int i = 0; i < 32; i += 8)
        dst[(size_t)(y + i) * rows + x] = t[threadIdx.x][threadIdx.y + i];
}

// ---------------- batchnorm: partial stats, then finalize ----------------
__global__ void __launch_bounds__(256)
bn_part_kernel(const float* __restrict__ q, float* __restrict__ part)
{
    const int lane32 = threadIdx.x & 31;
    const int grp = threadIdx.x >> 5;
    const int col = blockIdx.x * 32 + lane32;
    const int slice = blockIdx.y;
    const int r0 = slice * (N_TOK / 8);
    float s = 0.f, ss = 0.f;
    for (int r = grp; r < N_TOK / 8; r += 8) {
        float v = q[(size_t)(r0 + r) * DMODEL + col];
        s += v;
        ss += v * v;
    }
    __shared__ float sh_s[8][33], sh_q[8][33];
    sh_s[grp][lane32] = s;
    sh_q[grp][lane32] = ss;
    __syncthreads();
    if (grp == 0) {
        float ts = 0.f, tss = 0.f;
#pragma unroll
        for (int i = 0; i < 8; i++) { ts += sh_s[i][lane32]; tss += sh_q[i][lane32]; }
        part[(2 * slice + 0) * DMODEL + col] = ts;
        part[(2 * slice + 1) * DMODEL + col] = tss;
    }
}

__global__ void __launch_bounds__(256)
bn_final_kernel(const float* __restrict__ part,
                const float* __restrict__ gamma, const float* __restrict__ beta,
                float* __restrict__ scale, float* __restrict__ shift)
{
    const int col = blockIdx.x * 256 + threadIdx.x;
    float s = 0.f, ss = 0.f;
#pragma unroll
    for (int i = 0; i < 8; i++) {
        s  += part[(2 * i + 0) * DMODEL + col];
        ss += part[(2 * i + 1) * DMODEL + col];
    }
    float mean = s * (1.0f / N_TOK);
    float var = ss * (1.0f / N_TOK) - mean * mean;
    float rstd = rsqrtf(var + 1e-5f);
    float sc = gamma[col] * rstd;
    scale[col] = sc;
    shift[col] = beta[col] - mean * sc;
}

__global__ void __launch_bounds__(256)
normalize_kernel(float* __restrict__ q,
                 const float* __restrict__ scale, const float* __restrict__ shift)
{
    int i = blockIdx.x * blockDim.x + threadIdx.x;
    float4* q4 = reinterpret_cast<float4*>(q);
    float4 v = q4[i];
    int c = (i * 4) & (DMODEL - 1);
    v.x = v.x * scale[c + 0] + shift[c + 0];
    v.y = v.y * scale[c + 1] + shift[c + 1];
    v.z = v.z * scale[c + 2] + shift[c + 2];
    v.w = v.w * scale[c + 3] + shift[c + 3];
    q4[i] = v;
}

// ---------------- warp-collective top-16 of 128 values ----------------
__device__ __forceinline__ void warp_top16(const float* __restrict__ row,
                                           float* __restrict__ ov, int* __restrict__ oi,
                                           int lane)
{
    float v0 = row[lane], v1 = row[lane + 32], v2 = row[lane + 64], v3 = row[lane + 96];
#pragma unroll 1
    for (int it = 0; it < 16; it++) {
        float bv = v0; int bu = 0;
        if (v1 > bv) { bv = v1; bu = 1; }
        if (v2 > bv) { bv = v2; bu = 2; }
        if (v3 > bv) { bv = v3; bu = 3; }
        int bidx = lane + (bu << 5);
#pragma unroll
        for (int off = 16; off; off >>= 1) {
            float ovv = __shfl_down_sync(0xffffffffu, bv, off);
            int oii = __shfl_down_sync(0xffffffffu, bidx, off);
            if (ovv > bv) { bv = ovv; bidx = oii; }
        }
        bv = __shfl_sync(0xffffffffu, bv, 0);
        bidx = __shfl_sync(0xffffffffu, bidx, 0);
        if (lane == 0) { ov[it] = bv; oi[it] = bidx; }
        if ((bidx & 31) == lane) {
            int u = bidx >> 5;
            if (u == 0) v0 = NEG_INF;
            else if (u == 1) v1 = NEG_INF;
            else if (u == 2) v2 = NEG_INF;
            else v3 = NEG_INF;
        }
    }
}

__global__ void __launch_bounds__(256)
topk_kernel(const float* __restrict__ s1, const float* __restrict__ s2,
            float* __restrict__ probs, int* __restrict__ eidx)
{
    const int wid = threadIdx.x >> 5;
    const int lane = threadIdx.x & 31;
    const int row = blockIdx.x * 8 + wid;
    __shared__ float tv1[8][16], tv2[8][16];
    __shared__ int ti1[8][16], ti2[8][16];

    warp_top16(s1 + (size_t)row * NSUB, tv1[wid], ti1[wid], lane);
    warp_top16(s2 + (size_t)row * NSUB, tv2[wid], ti2[wid], lane);
    __syncwarp();

    float cv[8];
#pragma unroll
    for (int t = 0; t < 8; t++) {
        int c = lane * 8 + t;
        cv[t] = tv1[wid][c >> 4] + tv2[wid][c & 15];
    }
    float fv[8]; int fi[8];
#pragma unroll 1
    for (int it = 0; it < 8; it++) {
        float bv = cv[0]; int bt = 0;
#pragma unroll
        for (int t = 1; t < 8; t++) if (cv[t] > bv) { bv = cv[t]; bt = t; }
        int bidx = lane * 8 + bt;
#pragma unroll
        for (int off = 16; off; off >>= 1) {
            float ovv = __shfl_down_sync(0xffffffffu, bv, off);
            int oii = __shfl_down_sync(0xffffffffu, bidx, off);
            if (ovv > bv) { bv = ovv; bidx = oii; }
        }
        bv = __shfl_sync(0xffffffffu, bv, 0);
        bidx = __shfl_sync(0xffffffffu, bidx, 0);
        fv[it] = bv; fi[it] = bidx;
        if ((bidx >> 3) == lane) cv[bidx & 7] = NEG_INF;
    }

    if (lane < 8) {
        float m = fv[0];
        float sum = 0.f;
#pragma unroll
        for (int i = 0; i < 8; i++) sum += expf(fv[i] - m);
        float p = expf(fv[lane] - m) / sum;
        int c = fi[lane];
        int i1 = ti1[wid][c >> 4];
        int i2 = ti2[wid][c & 15];
        probs[(size_t)row * 8 + lane] = p;
        eidx[(size_t)row * 8 + lane] = i1 * NSUB + i2;
    }
}

// ---------------- MoE per-token: warp-per-expert, sync-free mainloop ----------------
__global__ void __launch_bounds__(256)
moe_kernel(const float* __restrict__ xproj, const float* __restrict__ Hall,
           const float* __restrict__ probs, const int* __restrict__ eidx,
           float* __restrict__ accb)
{
    const int n = blockIdx.x;
    const int t = threadIdx.x;
    const int lane = t & 31, w = t >> 5;
    __shared__ float part[8][DHIDDEN];

    float xpr[16];
#pragma unroll
    for (int j = 0; j < 16; j++)
        xpr[j] = xproj[(size_t)n * DHIDDEN + j * 32 + lane];

    float pa[16];
#pragma unroll
    for (int j = 0; j < 16; j++) pa[j] = 0.f;

#pragma unroll
    for (int je = 0; je < 4; je++) {
        const int s = w * 4 + je;
        const int e = eidx[n * 32 + s];
        const float* H = Hall + (size_t)e * DHIDDEN;
        float h[16];
#pragma unroll
        for (int j = 0; j < 16; j++) h[j] = H[j * 32 + lane];
        float dot = 0.f;
#pragma unroll
        for (int j = 0; j < 16; j++) dot = fmaf(xpr[j], h[j], dot);
#pragma unroll
        for (int off = 16; off; off >>= 1)
            dot += __shfl_xor_sync(0xffffffffu, dot, off);
        const float act = gelu_exact(dot) * probs[n * 32 + s];
#pragma unroll
        for (int j = 0; j < 16; j++) pa[j] = fmaf(act, h[j], pa[j]);
    }
#pragma unroll
    for (int j = 0; j < 16; j++) part[w][j * 32 + lane] = pa[j];
    __syncthreads();

    float a0 = 0.f, a1 = 0.f;
#pragma unroll
    for (int w2 = 0; w2 < 8; w2++) {
        a0 += part[w2][t];
        a1 += part[w2][t + 256];
    }
    accb[(size_t)n * DHIDDEN + t] = a0;
    accb[(size_t)n * DHIDDEN + 256 + t] = a1;
}

// ---------------- host launch ----------------
extern "C" void kernel_launch(void* const* d_in, const int* in_sizes, int n_in,
                              void* d_out, int out_size)
{
    const float* x       = (const float*)d_in[0];
    const float* Wq      = (const float*)d_in[1];
    const float* bq      = (const float*)d_in[2];
    const float* gamma   = (const float*)d_in[3];
    const float* beta    = (const float*)d_in[4];
    const float* sk1     = (const float*)d_in[5];
    const float* sk2     = (const float*)d_in[6];
    const float* latents = (const float*)d_in[7];
    const float* W1      = (const float*)d_in[8];
    const float* W2      = (const float*)d_in[9];
    float* out = (float*)d_out;

    void *pq, *ps1, *ps2, *psc, *psh, *pbp, *pH, *pxp, *pacc, *ppr, *pei, *pw1t, *pwvt;
    cudaGetSymbolAddress(&pq, g_q);
    cudaGetSymbolAddress(&ps1, g_s1);
    cudaGetSymbolAddress(&ps2, g_s2);
    cudaGetSymbolAddress(&psc, g_scale);
    cudaGetSymbolAddress(&psh, g_shift);
    cudaGetSymbolAddress(&pbp, g_bnpart);
    cudaGetSymbolAddress(&pH, g_Hall);
    cudaGetSymbolAddress(&pxp, g_xproj);
    cudaGetSymbolAddress(&pacc, g_acc);
    cudaGetSymbolAddress(&ppr, g_probs);
    cudaGetSymbolAddress(&pei, g_eidx);
    cudaGetSymbolAddress(&pw1t, g_W1T);
    cudaGetSymbolAddress(&pwvt, g_WvT);

    float* q_buf   = (float*)pq;
    float* s1_buf  = (float*)ps1;
    float* s2_buf  = (float*)ps2;
    float* sc_buf  = (float*)psc;
    float* sh_buf  = (float*)psh;
    float* bp_buf  = (float*)pbp;
    float* H_buf   = (float*)pH;
    float* xp_buf  = (float*)pxp;
    float* acc_buf = (float*)pacc;
    float* pr_buf  = (float*)ppr;
    int*   ei_buf  = (int*)pei;
    float* w1t_buf = (float*)pw1t;
    float* wvt_buf = (float*)pwvt;

    cudaFuncSetAttribute(fp16_gemm, cudaFuncAttributeMaxDynamicSharedMemorySize, GEMM4_SMEM);
    cudaFuncSetAttribute(hp2_gemm<0>, cudaFuncAttributeMaxDynamicSharedMemorySize, GEMM2_SMEM);
    cudaFuncSetAttribute(hp2_gemm<1>, cudaFuncAttributeMaxDynamicSharedMemorySize, GEMM2_SMEM);

    const dim3 blk(256);
    const dim3 tblk(32, 8);

    transpose_kernel<<<dim3(DHIDDEN / 32, DLATENT / 32), tblk>>>(W1, DHIDDEN, DLATENT, w1t_buf);
    transpose_kernel<<<dim3(DMODEL / 32, DHIDDEN / 32), tblk>>>(W2 + DMODEL, 2 * DMODEL, DHIDDEN, wvt_buf);

    // 1) q = x @ Wq^T + bq   (fp16x4)
    fp16_gemm<<<dim3(DMODEL / 128, N_TOK / 128), blk, GEMM4_SMEM>>>(
        x, DMODEL, Wq, DMODEL, q_buf, DMODEL, DMODEL, bq);

    // 2) batchnorm stats
    bn_part_kernel<<<dim3(DMODEL / 32, 8), blk>>>(q_buf, bp_buf);
    bn_final_kernel<<<DMODEL / 256, blk>>>(bp_buf, gamma, beta, sc_buf, sh_buf);

    // H_all = gelu(latents @ W1T^T)   (fp16x2, independent of scoring chain)
    hp2_gemm<1><<<dim3(DHIDDEN / 128, NEXPERTS / 128), blk, GEMM2_SMEM>>>(
        latents, DLATENT, w1t_buf, DLATENT, H_buf, DHIDDEN, DLATENT, nullptr, 1.0f);

    // 3) normalize
    normalize_kernel<<<(N_TOK * DMODEL / 4) / 256, blk>>>(q_buf, sc_buf, sh_buf);

    // 4) s1/s2 (fp16x4)
    fp16_gemm<<<dim3(1, (N_TOK * NHEADS) / 128), blk, GEMM4_SMEM>>>(
        q_buf, DQUERY, sk1, NSUB, s1_buf, NSUB, NSUB, nullptr);
    fp16_gemm<<<dim3(1, (N_TOK * NHEADS) / 128), blk, GEMM4_SMEM>>>(
        q_buf + 128, DQUERY, sk2, NSUB, s2_buf, NSUB, NSUB, nullptr);

    // 5) two-level top-k
    topk_kernel<<<(N_TOK * NHEADS) / 8, blk>>>(s1_buf, s2_buf, pr_buf, ei_buf);

    // 7) x_proj = x @ W2[:, :D]^T   (fp16x2)
    hp2_gemm<0><<<dim3(DHIDDEN / 128, N_TOK / 128), blk, GEMM2_SMEM>>>(
        x, DMODEL, W2, 2 * DMODEL, xp_buf, DHIDDEN, DMODEL, nullptr, 1.0f);

    // 8) MoE gather / act / accumulate
    moe_kernel<<<N_TOK, blk>>>(xp_buf, H_buf, pr_buf, ei_buf, acc_buf);

    // 9) out = acc @ WvT^T / 4   (fp16x2)
    hp2_gemm<0><<<dim3(DMODEL / 128, N_TOK / 128), blk, GEMM2_SMEM>>>(
        acc_buf, DHIDDEN, wvt_buf, DHIDDEN, out, DMODEL, DHIDDEN, nullptr, 0.25f);
}

// round 13
// speedup vs baseline: 1.5837x; 1.0513x over previous
#include <cuda_runtime.h>
#include <cuda_bf16.h>
#include <cuda_fp16.h>
#include <math.h>
#include <stdint.h>

#define N_TOK        8192
#define DMODEL       1024
#define DQUERY       256
#define NHEADS       4
#define NSUB         128
#define TOPK         8
#define DLATENT      256
#define DHIDDEN      512
#define NEXPERTS     16384
#define NEG_INF      (-1.0e38f)

// ---------------- scratch (device globals; no allocation allowed) ----------------
__device__ float g_q[N_TOK * DMODEL];
__device__ float g_s1[N_TOK * NHEADS * NSUB];
__device__ float g_s2[N_TOK * NHEADS * NSUB];
__device__ float g_scale[DMODEL];
__device__ float g_shift[DMODEL];
__device__ float g_bnpart[16 * DMODEL];
__device__ float g_Hall[NEXPERTS * DHIDDEN];
__device__ float g_xproj[N_TOK * DHIDDEN];
__device__ float g_acc[N_TOK * DHIDDEN];
__device__ float g_probs[N_TOK * NHEADS * TOPK];
__device__ int   g_eidx[N_TOK * NHEADS * TOPK];
__device__ float g_W1T[DHIDDEN * DLATENT];     // 512 x 256
__device__ float g_WvT[DMODEL * DHIDDEN];      // 1024 x 512

__device__ __forceinline__ float gelu_exact(float x) {
    return 0.5f * x * (1.0f + erff(x * 0.70710678118654752f));
}

__device__ __forceinline__ uint32_t smem_u32(const void* p) {
    uint32_t a;
    asm("{ .reg .u64 t; cvta.to.shared.u64 t, %1; cvt.u32.u64 %0, t; }" : "=r"(a) : "l"(p));
    return a;
}
__device__ __forceinline__ uint32_t sw128(uint32_t o) { return o ^ ((o >> 3) & 0x70); }

__device__ __forceinline__ void ldsm_x4(uint32_t* r, uint32_t addr) {
    asm volatile("ldmatrix.sync.aligned.m8n8.x4.shared.b16 {%0,%1,%2,%3}, [%4];"
                 : "=r"(r[0]), "=r"(r[1]), "=r"(r[2]), "=r"(r[3]) : "r"(addr));
}

// global chunk stage: 128 rows x 64 fp32 -> 8 float4 regs per thread
__device__ __forceinline__ void ch_ldg(const float* __restrict__ src, int ld,
                                       float4* r, int tid)
{
    const int r0 = tid >> 4;
    const int c  = (tid & 15) << 2;
#pragma unroll
    for (int p = 0; p < 8; p++)
        r[p] = *reinterpret_cast<const float4*>(src + (size_t)(r0 + (p << 4)) * ld + c);
}

__device__ __forceinline__ void mma16816h(float* d, const uint32_t* a, const uint32_t* b) {
    asm volatile(
        "mma.sync.aligned.m16n8k16.row.col.f32.f16.f16.f32 "
        "{%0,%1,%2,%3}, {%4,%5,%6,%7}, {%8,%9}, {%0,%1,%2,%3};"
        : "+f"(d[0]), "+f"(d[1]), "+f"(d[2]), "+f"(d[3])
        : "r"(a[0]), "r"(a[1]), "r"(a[2]), "r"(a[3]), "r"(b[0]), "r"(b[1]));
}

#define TILE_BYTES 16384
#define STAGE4_BYTES (4 * TILE_BYTES)
#define GEMM4_SMEM  (2 * STAGE4_BYTES + 1024)
#define STAGE2_BYTES (3 * TILE_BYTES)
#define GEMM2_SMEM  (2 * STAGE2_BYTES + 1024)

// split fp32 -> fp16 hi/lo, two swizzled tiles
__device__ __forceinline__ void hp_cvt_sts2(const float4* r,
                                            char* __restrict__ sm_hi,
                                            char* __restrict__ sm_lo, int tid)
{
    const int r0 = tid >> 4;
    const int c  = (tid & 15) << 2;
#pragma unroll
    for (int p = 0; p < 8; p++) {
        const int row = r0 + (p << 4);
        const float4 v = r[p];
        __half h0 = __float2half_rn(v.x);
        __half h1 = __float2half_rn(v.y);
        __half h2 = __float2half_rn(v.z);
        __half h3 = __float2half_rn(v.w);
        __half l0 = __float2half_rn(v.x - __half2float(h0));
        __half l1 = __float2half_rn(v.y - __half2float(h1));
        __half l2 = __float2half_rn(v.z - __half2float(h2));
        __half l3 = __float2half_rn(v.w - __half2float(h3));
        uint32_t hi01 = ((uint32_t)__half_as_ushort(h1) << 16) | __half_as_ushort(h0);
        uint32_t hi23 = ((uint32_t)__half_as_ushort(h3) << 16) | __half_as_ushort(h2);
        uint32_t lo01 = ((uint32_t)__half_as_ushort(l1) << 16) | __half_as_ushort(l0);
        uint32_t lo23 = ((uint32_t)__half_as_ushort(l3) << 16) | __half_as_ushort(l2);
        const uint32_t off = sw128((uint32_t)(row * 128 + (c << 1)));
        *reinterpret_cast<uint2*>(sm_hi + off) = make_uint2(hi01, hi23);
        *reinterpret_cast<uint2*>(sm_lo + off) = make_uint2(lo01, lo23);
    }
}

// round fp32 -> fp16, single swizzled tile
__device__ __forceinline__ void hp_cvt_sts1(const float4* r,
                                            char* __restrict__ sm_hi, int tid)
{
    const int r0 = tid >> 4;
    const int c  = (tid & 15) << 2;
#pragma unroll
    for (int p = 0; p < 8; p++) {
        const int row = r0 + (p << 4);
        const float4 v = r[p];
        uint32_t hi01 = ((uint32_t)__half_as_ushort(__float2half_rn(v.y)) << 16)
                      | __half_as_ushort(__float2half_rn(v.x));
        uint32_t hi23 = ((uint32_t)__half_as_ushort(__float2half_rn(v.w)) << 16)
                      | __half_as_ushort(__float2half_rn(v.z));
        const uint32_t off = sw128((uint32_t)(row * 128 + (c << 1)));
        *reinterpret_cast<uint2*>(sm_hi + off) = make_uint2(hi01, hi23);
    }
}

// ================================================================
// fp16x3 HMMA GEMM (scoring path — residual ~2^-22, tf32x3-grade)
// C = A*B^T + bias ; A: MxK fp32 (lda), B: NxK fp32 (ldb); K%64==0
// per-accumulator order: AhBh, AlBh, AhBl
// ================================================================
__global__ void __launch_bounds__(256, 1)
fp16_gemm(const float* __restrict__ A, int lda,
          const float* __restrict__ B, int ldb,
          float* __restrict__ C, int ldc, int K,
          const float* __restrict__ bias)
{
    extern __shared__ char dsm[];
    const uint32_t raw = smem_u32(dsm);
    const uint32_t base = (raw + 1023) & ~1023u;
    char* tiles = dsm + (base - raw);

    const int tid  = threadIdx.x;
    const int lane = tid & 31;
    const int wid  = tid >> 5;
    const int wm = wid & 3;
    const int wn = wid >> 2;
    const int bm = blockIdx.y * 128;
    const int bn = blockIdx.x * 128;

    const float* Ap = A + (size_t)bm * lda;
    const float* Bp = B + (size_t)bn * ldb;
    const int nk = K >> 6;

    float4 ra[8], rb[8];
    ch_ldg(Ap, lda, ra, tid);
    ch_ldg(Bp, ldb, rb, tid);
    hp_cvt_sts2(ra, tiles, tiles + TILE_BYTES, tid);
    hp_cvt_sts2(rb, tiles + 2 * TILE_BYTES, tiles + 3 * TILE_BYTES, tid);
    __syncthreads();

    float acc[2][8][4];
#pragma unroll
    for (int i = 0; i < 2; i++)
#pragma unroll
        for (int j = 0; j < 8; j++)
#pragma unroll
            for (int t = 0; t < 4; t++) acc[i][j][t] = 0.f;

    const int a_row = wm * 32 + (lane & 15);
    const int a_kb0 = (lane >> 4) << 4;
    const int b_row0 = wn * 64 + (lane & 7) + ((lane >> 4) << 3);
    const int b_kb0 = ((lane >> 3) & 1) << 4;

    for (int kc = 0; kc < nk; kc++) {
        const int cur = kc & 1;
        const bool more = (kc + 1 < nk);
        if (more) {
            ch_ldg(Ap + (kc + 1) * 64, lda, ra, tid);
            ch_ldg(Bp + (kc + 1) * 64, ldb, rb, tid);
        }
        const uint32_t sb = base + cur * STAGE4_BYTES;
#pragma unroll
        for (int ks = 0; ks < 4; ks++) {
            uint32_t Ah[2][4], Al[2][4];
#pragma unroll
            for (int mf = 0; mf < 2; mf++) {
                uint32_t off = sw128((uint32_t)((a_row + mf * 16) * 128 + ks * 32 + a_kb0));
                ldsm_x4(Ah[mf], sb + off);
                ldsm_x4(Al[mf], sb + TILE_BYTES + off);
            }
            uint32_t Bh[4][4], Bl[4][4];
#pragma unroll
            for (int nf2 = 0; nf2 < 4; nf2++) {
                uint32_t off = sw128((uint32_t)((b_row0 + nf2 * 16) * 128 + ks * 32 + b_kb0));
                ldsm_x4(Bh[nf2], sb + 2 * TILE_BYTES + off);
                ldsm_x4(Bl[nf2], sb + 3 * TILE_BYTES + off);
            }
            // per-accumulator order: AhBh, AlBh, AhBl
#pragma unroll
            for (int nf2 = 0; nf2 < 4; nf2++)
#pragma unroll
                for (int mf = 0; mf < 2; mf++) {
                    mma16816h(acc[mf][nf2 * 2 + 0], Ah[mf], Bh[nf2] + 0);
                    mma16816h(acc[mf][nf2 * 2 + 1], Ah[mf], Bh[nf2] + 2);
                }
#pragma unroll
            for (int nf2 = 0; nf2 < 4; nf2++)
#pragma unroll
                for (int mf = 0; mf < 2; mf++) {
                    mma16816h(acc[mf][nf2 * 2 + 0], Al[mf], Bh[nf2] + 0);
                    mma16816h(acc[mf][nf2 * 2 + 1], Al[mf], Bh[nf2] + 2);
                }
#pragma unroll
            for (int nf2 = 0; nf2 < 4; nf2++)
#pragma unroll
                for (int mf = 0; mf < 2; mf++) {
                    mma16816h(acc[mf][nf2 * 2 + 0], Ah[mf], Bl[nf2] + 0);
                    mma16816h(acc[mf][nf2 * 2 + 1], Ah[mf], Bl[nf2] + 2);
                }
        }
        if (more) {
            char* st = tiles + (cur ^ 1) * STAGE4_BYTES;
            hp_cvt_sts2(ra, st, st + TILE_BYTES, tid);
            hp_cvt_sts2(rb, st + 2 * TILE_BYTES, st + 3 * TILE_BYTES, tid);
        }
        __syncthreads();
    }

#pragma unroll
    for (int mf = 0; mf < 2; mf++) {
        const int row = bm + wm * 32 + mf * 16 + (lane >> 2);
#pragma unroll
        for (int nf = 0; nf < 8; nf++) {
            const int col = bn + wn * 64 + nf * 8 + (lane & 3) * 2;
            float b0 = 0.f, b1 = 0.f;
            if (bias) { b0 = bias[col]; b1 = bias[col + 1]; }
            *reinterpret_cast<float2*>(C + (size_t)row * ldc + col) =
                make_float2(acc[mf][nf][0] + b0, acc[mf][nf][1] + b1);
            *reinterpret_cast<float2*>(C + (size_t)(row + 8) * ldc + col) =
                make_float2(acc[mf][nf][2] + b0, acc[mf][nf][3] + b1);
        }
    }
}

// ================================================================
// fp16x2 HMMA GEMM (continuous GEMMs): A split hi/lo, B rounded
// per-accumulator order: AhBh, AlBh
// ================================================================
template<int ACT>   // 0 = none, 1 = gelu
__global__ void __launch_bounds__(256, 1)
hp2_gemm(const float* __restrict__ A, int lda,
         const float* __restrict__ B, int ldb,
         float* __restrict__ C, int ldc, int K,
         const float* __restrict__ bias, float scale)
{
    extern __shared__ char dsm[];
    const uint32_t raw = smem_u32(dsm);
    const uint32_t base = (raw + 1023) & ~1023u;
    char* tiles = dsm + (base - raw);

    const int tid  = threadIdx.x;
    const int lane = tid & 31;
    const int wid  = tid >> 5;
    const int wm = wid & 3;
    const int wn = wid >> 2;
    const int bm = blockIdx.y * 128;
    const int bn = blockIdx.x * 128;

    const float* Ap = A + (size_t)bm * lda;
    const float* Bp = B + (size_t)bn * ldb;
    const int nk = K >> 6;

    float4 ra[8], rb[8];
    ch_ldg(Ap, lda, ra, tid);
    ch_ldg(Bp, ldb, rb, tid);
    hp_cvt_sts2(ra, tiles, tiles + TILE_BYTES, tid);
    hp_cvt_sts1(rb, tiles + 2 * TILE_BYTES, tid);
    __syncthreads();

    float acc[2][8][4];
#pragma unroll
    for (int i = 0; i < 2; i++)
#pragma unroll
        for (int j = 0; j < 8; j++)
#pragma unroll
            for (int t = 0; t < 4; t++) acc[i][j][t] = 0.f;

    const int a_row = wm * 32 + (lane & 15);
    const int a_kb0 = (lane >> 4) << 4;
    const int b_row0 = wn * 64 + (lane & 7) + ((lane >> 4) << 3);
    const int b_kb0 = ((lane >> 3) & 1) << 4;

    for (int kc = 0; kc < nk; kc++) {
        const int cur = kc & 1;
        const bool more = (kc + 1 < nk);
        if (more) {
            ch_ldg(Ap + (kc + 1) * 64, lda, ra, tid);
            ch_ldg(Bp + (kc + 1) * 64, ldb, rb, tid);
        }
        const uint32_t sb = base + cur * STAGE2_BYTES;
#pragma unroll
        for (int ks = 0; ks < 4; ks++) {
            uint32_t Ah[2][4], Al[2][4];
#pragma unroll
            for (int mf = 0; mf < 2; mf++) {
                uint32_t off = sw128((uint32_t)((a_row + mf * 16) * 128 + ks * 32 + a_kb0));
                ldsm_x4(Ah[mf], sb + off);
                ldsm_x4(Al[mf], sb + TILE_BYTES + off);
            }
            uint32_t Bh[4][4];
#pragma unroll
            for (int nf2 = 0; nf2 < 4; nf2++) {
                uint32_t off = sw128((uint32_t)((b_row0 + nf2 * 16) * 128 + ks * 32 + b_kb0));
                ldsm_x4(Bh[nf2], sb + 2 * TILE_BYTES + off);
            }
#pragma unroll
            for (int nf2 = 0; nf2 < 4; nf2++)
#pragma unroll
                for (int mf = 0; mf < 2; mf++) {
                    mma16816h(acc[mf][nf2 * 2 + 0], Ah[mf], Bh[nf2] + 0);
                    mma16816h(acc[mf][nf2 * 2 + 1], Ah[mf], Bh[nf2] + 2);
                }
#pragma unroll
            for (int nf2 = 0; nf2 < 4; nf2++)
#pragma unroll
                for (int mf = 0; mf < 2; mf++) {
                    mma16816h(acc[mf][nf2 * 2 + 0], Al[mf], Bh[nf2] + 0);
                    mma16816h(acc[mf][nf2 * 2 + 1], Al[mf], Bh[nf2] + 2);
                }
        }
        if (more) {
            char* st = tiles + (cur ^ 1) * STAGE2_BYTES;
            hp_cvt_sts2(ra, st, st + TILE_BYTES, tid);
            hp_cvt_sts1(rb, st + 2 * TILE_BYTES, tid);
        }
        __syncthreads();
    }

#pragma unroll
    for (int mf = 0; mf < 2; mf++) {
        const int row = bm + wm * 32 + mf * 16 + (lane >> 2);
#pragma unroll
        for (int nf = 0; nf < 8; nf++) {
            const int col = bn + wn * 64 + nf * 8 + (lane & 3) * 2;
            float b0 = 0.f, b1 = 0.f;
            if (bias) { b0 = bias[col]; b1 = bias[col + 1]; }
            float v0 = acc[mf][nf][0] + b0;
            float v1 = acc[mf][nf][1] + b1;
            float v2 = acc[mf][nf][2] + b0;
            float v3 = acc[mf][nf][3] + b1;
            if (ACT == 1) {
                v0 = gelu_exact(v0); v1 = gelu_exact(v1);
                v2 = gelu_exact(v2); v3 = gelu_exact(v3);
            }
            v0 *= scale; v1 *= scale; v2 *= scale; v3 *= scale;
            *reinterpret_cast<float2*>(C + (size_t)row * ldc + col) = make_float2(v0, v1);
            *reinterpret_cast<float2*>(C + (size_t)(row + 8) * ldc + col) = make_float2(v2, v3);
        }
    }
}

// ---------------- transpose ----------------
__global__ void __launch_bounds__(256)
transpose_kernel(const float* __restrict__ src, int sld, int rows,
                 float* __restrict__ dst)
{
    __shared__ float t[32][33];
    const int bx = blockIdx.x * 32, by = blockIdx.y * 32;
    int x = bx + threadIdx.x, y = by + threadIdx.y;
#pragma unroll
    for (int i = 0; i < 32; i += 8)
        t[threadIdx.y + i][threadIdx.x] = src[(size_t)(y + i) * sld + x];
    __syncthreads();
    x = by + threadIdx.x; y = bx + threadIdx.y;
#pragma unroll
    for (int i = 0; i < 32; i += 8)
        dst[(size_t)(y + i) * rows + x] = t[threadIdx.x][threadIdx.y + i];
}

// ---------------- batchnorm: partial stats, then finalize ----------------
__global__ void __launch_bounds__(256)
bn_part_kernel(const float* __restrict__ q, float* __restrict__ part)
{
    const int lane32 = threadIdx.x & 31;
    const int grp = threadIdx.x >> 5;
    const int col = blockIdx.x * 32 + lane32;
    const int slice = blockIdx.y;
    const int r0 = slice * (N_TOK / 8);
    float s = 0.f, ss = 0.f;
    for (int r = grp; r < N_TOK / 8; r += 8) {
        float v = q[(size_t)(r0 + r) * DMODEL + col];
        s += v;
        ss += v * v;
    }
    __shared__ float sh_s[8][33], sh_q[8][33];
    sh_s[grp][lane32] = s;
    sh_q[grp][lane32] = ss;
    __syncthreads();
    if (grp == 0) {
        float ts = 0.f, tss = 0.f;
#pragma unroll
        for (int i = 0; i < 8; i++) { ts += sh_s[i][lane32]; tss += sh_q[i][lane32]; }
        part[(2 * slice + 0) * DMODEL + col] = ts;
        part[(2 * slice + 1) * DMODEL + col] = tss;
    }
}

__global__ void __launch_bounds__(256)
bn_final_kernel(const float* __restrict__ part,
                const float* __restrict__ gamma, const float* __restrict__ beta,
                float* __restrict__ scale, float* __restrict__ shift)
{
    const int col = blockIdx.x * 256 + threadIdx.x;
    float s = 0.f, ss = 0.f;
#pragma unroll
    for (int i = 0; i < 8; i++) {
        s  += part[(2 * i + 0) * DMODEL + col];
        ss += part[(2 * i + 1) * DMODEL + col];
    }
    float mean = s * (1.0f / N_TOK);
    float var = ss * (1.0f / N_TOK) - mean * mean;
    float rstd = rsqrtf(var + 1e-5f);
    float sc = gamma[col] * rstd;
    scale[col] = sc;
    shift[col] = beta[col] - mean * sc;
}

__global__ void __launch_bounds__(256)
normalize_kernel(float* __restrict__ q,
                 const float* __restrict__ scale, const float* __restrict__ shift)
{
    int i = blockIdx.x * blockDim.x + threadIdx.x;
    float4* q4 = reinterpret_cast<float4*>(q);
    float4 v = q4[i];
    int c = (i * 4) & (DMODEL - 1);
    v.x = v.x * scale[c + 0] + shift[c + 0];
    v.y = v.y * scale[c + 1] + shift[c + 1];
    v.z = v.z * scale[c + 2] + shift[c + 2];
    v.w = v.w * scale[c + 3] + shift[c + 3];
    q4[i] = v;
}

// ---------------- warp-collective top-16 of 128 values ----------------
__device__ __forceinline__ void warp_top16(const float* __restrict__ row,
                                           float* __restrict__ ov, int* __restrict__ oi,
                                           int lane)
{
    float v0 = row[lane], v1 = row[lane + 32], v2 = row[lane + 64], v3 = row[lane + 96];
#pragma unroll 1
    for (int it = 0; it < 16; it++) {
        float bv = v0; int bu = 0;
        if (v1 > bv) { bv = v1; bu = 1; }
        if (v2 > bv) { bv = v2; bu = 2; }
        if (v3 > bv) { bv = v3; bu = 3; }
        int bidx = lane + (bu << 5);
#pragma unroll
        for (int off = 16; off; off >>= 1) {
            float ovv = __shfl_down_sync(0xffffffffu, bv, off);
            int oii = __shfl_down_sync(0xffffffffu, bidx, off);
            if (ovv > bv) { bv = ovv; bidx = oii; }
        }
        bv = __shfl_sync(0xffffffffu, bv, 0);
        bidx = __shfl_sync(0xffffffffu, bidx, 0);
        if (lane == 0) { ov[it] = bv; oi[it] = bidx; }
        if ((bidx & 31) == lane) {
            int u = bidx >> 5;
            if (u == 0) v0 = NEG_INF;
            else if (u == 1) v1 = NEG_INF;
            else if (u == 2) v2 = NEG_INF;
            else v3 = NEG_INF;
        }
    }
}

__global__ void __launch_bounds__(256)
topk_kernel(const float* __restrict__ s1, const float* __restrict__ s2,
            float* __restrict__ probs, int* __restrict__ eidx)
{
    const int wid = threadIdx.x >> 5;
    const int lane = threadIdx.x & 31;
    const int row = blockIdx.x * 8 + wid;
    __shared__ float tv1[8][16], tv2[8][16];
    __shared__ int ti1[8][16], ti2[8][16];

    warp_top16(s1 + (size_t)row * NSUB, tv1[wid], ti1[wid], lane);
    warp_top16(s2 + (size_t)row * NSUB, tv2[wid], ti2[wid], lane);
    __syncwarp();

    float cv[8];
#pragma unroll
    for (int t = 0; t < 8; t++) {
        int c = lane * 8 + t;
        cv[t] = tv1[wid][c >> 4] + tv2[wid][c & 15];
    }
    float fv[8]; int fi[8];
#pragma unroll 1
    for (int it = 0; it < 8; it++) {
        float bv = cv[0]; int bt = 0;
#pragma unroll
        for (int t = 1; t < 8; t++) if (cv[t] > bv) { bv = cv[t]; bt = t; }
        int bidx = lane * 8 + bt;
#pragma unroll
        for (int off = 16; off; off >>= 1) {
            float ovv = __shfl_down_sync(0xffffffffu, bv, off);
            int oii = __shfl_down_sync(0xffffffffu, bidx, off);
            if (ovv > bv) { bv = ovv; bidx = oii; }
        }
        bv = __shfl_sync(0xffffffffu, bv, 0);
        bidx = __shfl_sync(0xffffffffu, bidx, 0);
        fv[it] = bv; fi[it] = bidx;
        if ((bidx >> 3) == lane) cv[bidx & 7] = NEG_INF;
    }

    if (lane < 8) {
        float m = fv[0];
        float sum = 0.f;
#pragma unroll
        for (int i = 0; i < 8; i++) sum += expf(fv[i] - m);
        float p = expf(fv[lane] - m) / sum;
        int c = fi[lane];
        int i1 = ti1[wid][c >> 4];
        int i2 = ti2[wid][c & 15];
        probs[(size_t)row * 8 + lane] = p;
        eidx[(size_t)row * 8 + lane] = i1 * NSUB + i2;
    }
}

// ---------------- MoE per-token: warp-per-expert, sync-free mainloop ----------------
__global__ void __launch_bounds__(256)
moe_kernel(const float* __restrict__ xproj, const float* __restrict__ Hall,
           const float* __restrict__ probs, const int* __restrict__ eidx,
           float* __restrict__ accb)
{
    const int n = blockIdx.x;
    const int t = threadIdx.x;
    const int lane = t & 31, w = t >> 5;
    __shared__ float part[8][DHIDDEN];

    float xpr[16];
#pragma unroll
    for (int j = 0; j < 16; j++)
        xpr[j] = xproj[(size_t)n * DHIDDEN + j * 32 + lane];

    float pa[16];
#pragma unroll
    for (int j = 0; j < 16; j++) pa[j] = 0.f;

#pragma unroll
    for (int je = 0; je < 4; je++) {
        const int s = w * 4 + je;
        const int e = eidx[n * 32 + s];
        const float* H = Hall + (size_t)e * DHIDDEN;
        float h[16];
#pragma unroll
        for (int j = 0; j < 16; j++) h[j] = H[j * 32 + lane];
        float dot = 0.f;
#pragma unroll
        for (int j = 0; j < 16; j++) dot = fmaf(xpr[j], h[j], dot);
#pragma unroll
        for (int off = 16; off; off >>= 1)
            dot += __shfl_xor_sync(0xffffffffu, dot, off);
        const float act = gelu_exact(dot) * probs[n * 32 + s];
#pragma unroll
        for (int j = 0; j < 16; j++) pa[j] = fmaf(act, h[j], pa[j]);
    }
#pragma unroll
    for (int j = 0; j < 16; j++) part[w][j * 32 + lane] = pa[j];
    __syncthreads();

    float a0 = 0.f, a1 = 0.f;
#pragma unroll
    for (int w2 = 0; w2 < 8; w2++) {
        a0 += part[w2][t];
        a1 += part[w2][t + 256];
    }
    accb[(size_t)n * DHIDDEN + t] = a0;
    accb[(size_t)n * DHIDDEN + 256 + t] = a1;
}

// ---------------- host launch ----------------
extern "C" void kernel_launch(void* const* d_in, const int* in_sizes, int n_in,
                              void* d_out, int out_size)
{
    const float* x       = (const float*)d_in[0];
    const float* Wq      = (const float*)d_in[1];
    const float* bq      = (const float*)d_in[2];
    const float* gamma   = (const float*)d_in[3];
    const float* beta    = (const float*)d_in[4];
    const float* sk1     = (const float*)d_in[5];
    const float* sk2     = (const float*)d_in[6];
    const float* latents = (const float*)d_in[7];
    const float* W1      = (const float*)d_in[8];
    const float* W2      = (const float*)d_in[9];
    float* out = (float*)d_out;

    void *pq, *ps1, *ps2, *psc, *psh, *pbp, *pH, *pxp, *pacc, *ppr, *pei, *pw1t, *pwvt;
    cudaGetSymbolAddress(&pq, g_q);
    cudaGetSymbolAddress(&ps1, g_s1);
    cudaGetSymbolAddress(&ps2, g_s2);
    cudaGetSymbolAddress(&psc, g_scale);
    cudaGetSymbolAddress(&psh, g_shift);
    cudaGetSymbolAddress(&pbp, g_bnpart);
    cudaGetSymbolAddress(&pH, g_Hall);
    cudaGetSymbolAddress(&pxp, g_xproj);
    cudaGetSymbolAddress(&pacc, g_acc);
    cudaGetSymbolAddress(&ppr, g_probs);
    cudaGetSymbolAddress(&pei, g_eidx);
    cudaGetSymbolAddress(&pw1t, g_W1T);
    cudaGetSymbolAddress(&pwvt, g_WvT);

    float* q_buf   = (float*)pq;
    float* s1_buf  = (float*)ps1;
    float* s2_buf  = (float*)ps2;
    float* sc_buf  = (float*)psc;
    float* sh_buf  = (float*)psh;
    float* bp_buf  = (float*)pbp;
    float* H_buf   = (float*)pH;
    float* xp_buf  = (float*)pxp;
    float* acc_buf = (float*)pacc;
    float* pr_buf  = (float*)ppr;
    int*   ei_buf  = (int*)pei;
    float* w1t_buf = (float*)pw1t;
    float* wvt_buf = (float*)pwvt;

    cudaFuncSetAttribute(fp16_gemm, cudaFuncAttributeMaxDynamicSharedMemorySize, GEMM4_SMEM);
    cudaFuncSetAttribute(hp2_gemm<0>, cudaFuncAttributeMaxDynamicSharedMemorySize, GEMM2_SMEM);
    cudaFuncSetAttribute(hp2_gemm<1>, cudaFuncAttributeMaxDynamicSharedMemorySize, GEMM2_SMEM);

    const dim3 blk(256);
    const dim3 tblk(32, 8);

    transpose_kernel<<<dim3(DHIDDEN / 32, DLATENT / 32), tblk>>>(W1, DHIDDEN, DLATENT, w1t_buf);
    transpose_kernel<<<dim3(DMODEL / 32, DHIDDEN / 32), tblk>>>(W2 + DMODEL, 2 * DMODEL, DHIDDEN, wvt_buf);

    // 1) q = x @ Wq^T + bq   (fp16x3)
    fp16_gemm<<<dim3(DMODEL / 128, N_TOK / 128), blk, GEMM4_SMEM>>>(
        x, DMODEL, Wq, DMODEL, q_buf, DMODEL, DMODEL, bq);

    // 2) batchnorm stats
    bn_part_kernel<<<dim3(DMODEL / 32, 8), blk>>>(q_buf, bp_buf);
    bn_final_kernel<<<DMODEL / 256, blk>>>(bp_buf, gamma, beta, sc_buf, sh_buf);

    // H_all = gelu(latents @ W1T^T)   (fp16x2, independent of scoring chain)
    hp2_gemm<1><<<dim3(DHIDDEN / 128, NEXPERTS / 128), blk, GEMM2_SMEM>>>(
        latents, DLATENT, w1t_buf, DLATENT, H_buf, DHIDDEN, DLATENT, nullptr, 1.0f);

    // 3) normalize
    normalize_kernel<<<(N_TOK * DMODEL / 4) / 256, blk>>>(q_buf, sc_buf, sh_buf);

    // 4) s1/s2 (fp16x3)
    fp16_gemm<<<dim3(1, (N_TOK * NHEADS) / 128), blk, GEMM4_SMEM>>>(
        q_buf, DQUERY, sk1, NSUB, s1_buf, NSUB, NSUB, nullptr);
    fp16_gemm<<<dim3(1, (N_TOK * NHEADS) / 128), blk, GEMM4_SMEM>>>(
        q_buf + 128, DQUERY, sk2, NSUB, s2_buf, NSUB, NSUB, nullptr);

    // 5) two-level top-k
    topk_kernel<<<(N_TOK * NHEADS) / 8, blk>>>(s1_buf, s2_buf, pr_buf, ei_buf);

    // 7) x_proj = x @ W2[:, :D]^T   (fp16x2)
    hp2_gemm<0><<<dim3(DHIDDEN / 128, N_TOK / 128), blk, GEMM2_SMEM>>>(
        x, DMODEL, W2, 2 * DMODEL, xp_buf, DHIDDEN, DMODEL, nullptr, 1.0f);

    // 8) MoE gather / act / accumulate
    moe_kernel<<<N_TOK, blk>>>(xp_buf, H_buf, pr_buf, ei_buf, acc_buf);

    // 9) out = acc @ WvT^T / 4   (fp16x2)
    hp2_gemm<0><<<dim3(DMODEL / 128, N_TOK / 128), blk, GEMM2_SMEM>>>(
        acc_buf, DHIDDEN, wvt_buf, DHIDDEN, out, DMODEL, DHIDDEN, nullptr, 0.25f);
}

// round 14
// speedup vs baseline: 1.6623x; 1.0496x over previous
#include <cuda_runtime.h>
#include <cuda_bf16.h>
#include <cuda_fp16.h>
#include <math.h>
#include <stdint.h>

#define N_TOK        8192
#define DMODEL       1024
#define DQUERY       256
#define NHEADS       4
#define NSUB         128
#define TOPK         8
#define DLATENT      256
#define DHIDDEN      512
#define NEXPERTS     16384
#define NEG_INF      (-1.0e38f)

// ---------------- scratch (device globals; no allocation allowed) ----------------
__device__ float g_q[N_TOK * DMODEL];
__device__ float g_s1[N_TOK * NHEADS * NSUB];
__device__ float g_s2[N_TOK * NHEADS * NSUB];
__device__ float g_scale[DMODEL];
__device__ float g_shift[DMODEL];
__device__ float g_bnpart[16 * DMODEL];
__device__ float g_Hall[NEXPERTS * DHIDDEN];
__device__ float g_xproj[N_TOK * DHIDDEN];
__device__ float g_acc[N_TOK * DHIDDEN];
__device__ float g_probs[N_TOK * NHEADS * TOPK];
__device__ int   g_eidx[N_TOK * NHEADS * TOPK];
__device__ float g_W1T[DHIDDEN * DLATENT];     // 512 x 256
__device__ float g_WvT[DMODEL * DHIDDEN];      // 1024 x 512

__device__ __forceinline__ float gelu_exact(float x) {
    return 0.5f * x * (1.0f + erff(x * 0.70710678118654752f));
}

__device__ __forceinline__ uint32_t smem_u32(const void* p) {
    uint32_t a;
    asm("{ .reg .u64 t; cvta.to.shared.u64 t, %1; cvt.u32.u64 %0, t; }" : "=r"(a) : "l"(p));
    return a;
}
__device__ __forceinline__ uint32_t sw128(uint32_t o) { return o ^ ((o >> 3) & 0x70); }

__device__ __forceinline__ void ldsm_x4(uint32_t* r, uint32_t addr) {
    asm volatile("ldmatrix.sync.aligned.m8n8.x4.shared.b16 {%0,%1,%2,%3}, [%4];"
                 : "=r"(r[0]), "=r"(r[1]), "=r"(r[2]), "=r"(r[3]) : "r"(addr));
}

// global chunk stage: 128 rows x 64 fp32 -> 8 float4 regs per thread
__device__ __forceinline__ void ch_ldg(const float* __restrict__ src, int ld,
                                       float4* r, int tid)
{
    const int r0 = tid >> 4;
    const int c  = (tid & 15) << 2;
#pragma unroll
    for (int p = 0; p < 8; p++)
        r[p] = *reinterpret_cast<const float4*>(src + (size_t)(r0 + (p << 4)) * ld + c);
}

__device__ __forceinline__ void mma16816h(float* d, const uint32_t* a, const uint32_t* b) {
    asm volatile(
        "mma.sync.aligned.m16n8k16.row.col.f32.f16.f16.f32 "
        "{%0,%1,%2,%3}, {%4,%5,%6,%7}, {%8,%9}, {%0,%1,%2,%3};"
        : "+f"(d[0]), "+f"(d[1]), "+f"(d[2]), "+f"(d[3])
        : "r"(a[0]), "r"(a[1]), "r"(a[2]), "r"(a[3]), "r"(b[0]), "r"(b[1]));
}

#define TILE_BYTES 16384
#define STAGE4_BYTES (4 * TILE_BYTES)
#define GEMM4_SMEM  (2 * STAGE4_BYTES + 1024)
#define STAGE1_BYTES (2 * TILE_BYTES)
#define GEMM1_SMEM  (2 * STAGE1_BYTES + 1024)

// split fp32 -> fp16 hi/lo, two swizzled tiles
__device__ __forceinline__ void hp_cvt_sts2(const float4* r,
                                            char* __restrict__ sm_hi,
                                            char* __restrict__ sm_lo, int tid)
{
    const int r0 = tid >> 4;
    const int c  = (tid & 15) << 2;
#pragma unroll
    for (int p = 0; p < 8; p++) {
        const int row = r0 + (p << 4);
        const float4 v = r[p];
        __half h0 = __float2half_rn(v.x);
        __half h1 = __float2half_rn(v.y);
        __half h2 = __float2half_rn(v.z);
        __half h3 = __float2half_rn(v.w);
        __half l0 = __float2half_rn(v.x - __half2float(h0));
        __half l1 = __float2half_rn(v.y - __half2float(h1));
        __half l2 = __float2half_rn(v.z - __half2float(h2));
        __half l3 = __float2half_rn(v.w - __half2float(h3));
        uint32_t hi01 = ((uint32_t)__half_as_ushort(h1) << 16) | __half_as_ushort(h0);
        uint32_t hi23 = ((uint32_t)__half_as_ushort(h3) << 16) | __half_as_ushort(h2);
        uint32_t lo01 = ((uint32_t)__half_as_ushort(l1) << 16) | __half_as_ushort(l0);
        uint32_t lo23 = ((uint32_t)__half_as_ushort(l3) << 16) | __half_as_ushort(l2);
        const uint32_t off = sw128((uint32_t)(row * 128 + (c << 1)));
        *reinterpret_cast<uint2*>(sm_hi + off) = make_uint2(hi01, hi23);
        *reinterpret_cast<uint2*>(sm_lo + off) = make_uint2(lo01, lo23);
    }
}

// round fp32 -> fp16, single swizzled tile
__device__ __forceinline__ void hp_cvt_sts1(const float4* r,
                                            char* __restrict__ sm_hi, int tid)
{
    const int r0 = tid >> 4;
    const int c  = (tid & 15) << 2;
#pragma unroll
    for (int p = 0; p < 8; p++) {
        const int row = r0 + (p << 4);
        const float4 v = r[p];
        uint32_t hi01 = ((uint32_t)__half_as_ushort(__float2half_rn(v.y)) << 16)
                      | __half_as_ushort(__float2half_rn(v.x));
        uint32_t hi23 = ((uint32_t)__half_as_ushort(__float2half_rn(v.w)) << 16)
                      | __half_as_ushort(__float2half_rn(v.z));
        const uint32_t off = sw128((uint32_t)(row * 128 + (c << 1)));
        *reinterpret_cast<uint2*>(sm_hi + off) = make_uint2(hi01, hi23);
    }
}

// ================================================================
// fp16x3 HMMA GEMM (scoring path — residual ~2^-22)
// C = A*B^T + bias ; A: MxK fp32 (lda), B: NxK fp32 (ldb); K%64==0
// per-accumulator order: AhBh, AlBh, AhBl
// ================================================================
__global__ void __launch_bounds__(256, 1)
fp16_gemm(const float* __restrict__ A, int lda,
          const float* __restrict__ B, int ldb,
          float* __restrict__ C, int ldc, int K,
          const float* __restrict__ bias)
{
    extern __shared__ char dsm[];
    const uint32_t raw = smem_u32(dsm);
    const uint32_t base = (raw + 1023) & ~1023u;
    char* tiles = dsm + (base - raw);

    const int tid  = threadIdx.x;
    const int lane = tid & 31;
    const int wid  = tid >> 5;
    const int wm = wid & 3;
    const int wn = wid >> 2;
    const int bm = blockIdx.y * 128;
    const int bn = blockIdx.x * 128;

    const float* Ap = A + (size_t)bm * lda;
    const float* Bp = B + (size_t)bn * ldb;
    const int nk = K >> 6;

    float4 ra[8], rb[8];
    ch_ldg(Ap, lda, ra, tid);
    ch_ldg(Bp, ldb, rb, tid);
    hp_cvt_sts2(ra, tiles, tiles + TILE_BYTES, tid);
    hp_cvt_sts2(rb, tiles + 2 * TILE_BYTES, tiles + 3 * TILE_BYTES, tid);
    __syncthreads();

    float acc[2][8][4];
#pragma unroll
    for (int i = 0; i < 2; i++)
#pragma unroll
        for (int j = 0; j < 8; j++)
#pragma unroll
            for (int t = 0; t < 4; t++) acc[i][j][t] = 0.f;

    const int a_row = wm * 32 + (lane & 15);
    const int a_kb0 = (lane >> 4) << 4;
    const int b_row0 = wn * 64 + (lane & 7) + ((lane >> 4) << 3);
    const int b_kb0 = ((lane >> 3) & 1) << 4;

    for (int kc = 0; kc < nk; kc++) {
        const int cur = kc & 1;
        const bool more = (kc + 1 < nk);
        if (more) {
            ch_ldg(Ap + (kc + 1) * 64, lda, ra, tid);
            ch_ldg(Bp + (kc + 1) * 64, ldb, rb, tid);
        }
        const uint32_t sb = base + cur * STAGE4_BYTES;
#pragma unroll
        for (int ks = 0; ks < 4; ks++) {
            uint32_t Ah[2][4], Al[2][4];
#pragma unroll
            for (int mf = 0; mf < 2; mf++) {
                uint32_t off = sw128((uint32_t)((a_row + mf * 16) * 128 + ks * 32 + a_kb0));
                ldsm_x4(Ah[mf], sb + off);
                ldsm_x4(Al[mf], sb + TILE_BYTES + off);
            }
            uint32_t Bh[4][4], Bl[4][4];
#pragma unroll
            for (int nf2 = 0; nf2 < 4; nf2++) {
                uint32_t off = sw128((uint32_t)((b_row0 + nf2 * 16) * 128 + ks * 32 + b_kb0));
                ldsm_x4(Bh[nf2], sb + 2 * TILE_BYTES + off);
                ldsm_x4(Bl[nf2], sb + 3 * TILE_BYTES + off);
            }
            // per-accumulator order: AhBh, AlBh, AhBl
#pragma unroll
            for (int nf2 = 0; nf2 < 4; nf2++)
#pragma unroll
                for (int mf = 0; mf < 2; mf++) {
                    mma16816h(acc[mf][nf2 * 2 + 0], Ah[mf], Bh[nf2] + 0);
                    mma16816h(acc[mf][nf2 * 2 + 1], Ah[mf], Bh[nf2] + 2);
                }
#pragma unroll
            for (int nf2 = 0; nf2 < 4; nf2++)
#pragma unroll
                for (int mf = 0; mf < 2; mf++) {
                    mma16816h(acc[mf][nf2 * 2 + 0], Al[mf], Bh[nf2] + 0);
                    mma16816h(acc[mf][nf2 * 2 + 1], Al[mf], Bh[nf2] + 2);
                }
#pragma unroll
            for (int nf2 = 0; nf2 < 4; nf2++)
#pragma unroll
                for (int mf = 0; mf < 2; mf++) {
                    mma16816h(acc[mf][nf2 * 2 + 0], Ah[mf], Bl[nf2] + 0);
                    mma16816h(acc[mf][nf2 * 2 + 1], Ah[mf], Bl[nf2] + 2);
                }
        }
        if (more) {
            char* st = tiles + (cur ^ 1) * STAGE4_BYTES;
            hp_cvt_sts2(ra, st, st + TILE_BYTES, tid);
            hp_cvt_sts2(rb, st + 2 * TILE_BYTES, st + 3 * TILE_BYTES, tid);
        }
        __syncthreads();
    }

#pragma unroll
    for (int mf = 0; mf < 2; mf++) {
        const int row = bm + wm * 32 + mf * 16 + (lane >> 2);
#pragma unroll
        for (int nf = 0; nf < 8; nf++) {
            const int col = bn + wn * 64 + nf * 8 + (lane & 3) * 2;
            float b0 = 0.f, b1 = 0.f;
            if (bias) { b0 = bias[col]; b1 = bias[col + 1]; }
            *reinterpret_cast<float2*>(C + (size_t)row * ldc + col) =
                make_float2(acc[mf][nf][0] + b0, acc[mf][nf][1] + b1);
            *reinterpret_cast<float2*>(C + (size_t)(row + 8) * ldc + col) =
                make_float2(acc[mf][nf][2] + b0, acc[mf][nf][3] + b1);
        }
    }
}

// ================================================================
// fp16x1 HMMA GEMM (continuous GEMMs): A rounded, B rounded
// ================================================================
template<int ACT>   // 0 = none, 1 = gelu
__global__ void __launch_bounds__(256, 1)
hp1_gemm(const float* __restrict__ A, int lda,
         const float* __restrict__ B, int ldb,
         float* __restrict__ C, int ldc, int K,
         const float* __restrict__ bias, float scale)
{
    extern __shared__ char dsm[];
    const uint32_t raw = smem_u32(dsm);
    const uint32_t base = (raw + 1023) & ~1023u;
    char* tiles = dsm + (base - raw);

    const int tid  = threadIdx.x;
    const int lane = tid & 31;
    const int wid  = tid >> 5;
    const int wm = wid & 3;
    const int wn = wid >> 2;
    const int bm = blockIdx.y * 128;
    const int bn = blockIdx.x * 128;

    const float* Ap = A + (size_t)bm * lda;
    const float* Bp = B + (size_t)bn * ldb;
    const int nk = K >> 6;

    float4 ra[8], rb[8];
    ch_ldg(Ap, lda, ra, tid);
    ch_ldg(Bp, ldb, rb, tid);
    hp_cvt_sts1(ra, tiles, tid);
    hp_cvt_sts1(rb, tiles + TILE_BYTES, tid);
    __syncthreads();

    float acc[2][8][4];
#pragma unroll
    for (int i = 0; i < 2; i++)
#pragma unroll
        for (int j = 0; j < 8; j++)
#pragma unroll
            for (int t = 0; t < 4; t++) acc[i][j][t] = 0.f;

    const int a_row = wm * 32 + (lane & 15);
    const int a_kb0 = (lane >> 4) << 4;
    const int b_row0 = wn * 64 + (lane & 7) + ((lane >> 4) << 3);
    const int b_kb0 = ((lane >> 3) & 1) << 4;

    for (int kc = 0; kc < nk; kc++) {
        const int cur = kc & 1;
        const bool more = (kc + 1 < nk);
        if (more) {
            ch_ldg(Ap + (kc + 1) * 64, lda, ra, tid);
            ch_ldg(Bp + (kc + 1) * 64, ldb, rb, tid);
        }
        const uint32_t sb = base + cur * STAGE1_BYTES;
#pragma unroll
        for (int ks = 0; ks < 4; ks++) {
            uint32_t Ah[2][4];
#pragma unroll
            for (int mf = 0; mf < 2; mf++) {
                uint32_t off = sw128((uint32_t)((a_row + mf * 16) * 128 + ks * 32 + a_kb0));
                ldsm_x4(Ah[mf], sb + off);
            }
            uint32_t Bh[4][4];
#pragma unroll
            for (int nf2 = 0; nf2 < 4; nf2++) {
                uint32_t off = sw128((uint32_t)((b_row0 + nf2 * 16) * 128 + ks * 32 + b_kb0));
                ldsm_x4(Bh[nf2], sb + TILE_BYTES + off);
            }
#pragma unroll
            for (int nf2 = 0; nf2 < 4; nf2++)
#pragma unroll
                for (int mf = 0; mf < 2; mf++) {
                    mma16816h(acc[mf][nf2 * 2 + 0], Ah[mf], Bh[nf2] + 0);
                    mma16816h(acc[mf][nf2 * 2 + 1], Ah[mf], Bh[nf2] + 2);
                }
        }
        if (more) {
            char* st = tiles + (cur ^ 1) * STAGE1_BYTES;
            hp_cvt_sts1(ra, st, tid);
            hp_cvt_sts1(rb, st + TILE_BYTES, tid);
        }
        __syncthreads();
    }

#pragma unroll
    for (int mf = 0; mf < 2; mf++) {
        const int row = bm + wm * 32 + mf * 16 + (lane >> 2);
#pragma unroll
        for (int nf = 0; nf < 8; nf++) {
            const int col = bn + wn * 64 + nf * 8 + (lane & 3) * 2;
            float b0 = 0.f, b1 = 0.f;
            if (bias) { b0 = bias[col]; b1 = bias[col + 1]; }
            float v0 = acc[mf][nf][0] + b0;
            float v1 = acc[mf][nf][1] + b1;
            float v2 = acc[mf][nf][2] + b0;
            float v3 = acc[mf][nf][3] + b1;
            if (ACT == 1) {
                v0 = gelu_exact(v0); v1 = gelu_exact(v1);
                v2 = gelu_exact(v2); v3 = gelu_exact(v3);
            }
            v0 *= scale; v1 *= scale; v2 *= scale; v3 *= scale;
            *reinterpret_cast<float2*>(C + (size_t)row * ldc + col) = make_float2(v0, v1);
            *reinterpret_cast<float2*>(C + (size_t)(row + 8) * ldc + col) = make_float2(v2, v3);
        }
    }
}

// ---------------- transpose ----------------
__global__ void __launch_bounds__(256)
transpose_kernel(const float* __restrict__ src, int sld, int rows,
                 float* __restrict__ dst)
{
    __shared__ float t[32][33];
    const int bx = blockIdx.x * 32, by = blockIdx.y * 32;
    int x = bx + threadIdx.x, y = by + threadIdx.y;
#pragma unroll
    for (int i = 0; i < 32; i += 8)
        t[threadIdx.y + i][threadIdx.x] = src[(size_t)(y + i) * sld + x];
    __syncthreads();
    x = by + threadIdx.x; y = bx + threadIdx.y;
#pragma unroll
    for (int i = 0; i < 32; i += 8)
        dst[(size_t)(y + i) * rows + x] = t[threadIdx.x][threadIdx.y + i];
}

// ---------------- batchnorm: partial stats, then finalize ----------------
__global__ void __launch_bounds__(256)
bn_part_kernel(const float* __restrict__ q, float* __restrict__ part)
{
    const int lane32 = threadIdx.x & 31;
    const int grp = threadIdx.x >> 5;
    const int col = blockIdx.x * 32 + lane32;
    const int slice = blockIdx.y;
    const int r0 = slice * (N_TOK / 8);
    float s = 0.f, ss = 0.f;
    for (int r = grp; r < N_TOK / 8; r += 8) {
        float v = q[(size_t)(r0 + r) * DMODEL + col];
        s += v;
        ss += v * v;
    }
    __shared__ float sh_s[8][33], sh_q[8][33];
    sh_s[grp][lane32] = s;
    sh_q[grp][lane32] = ss;
    __syncthreads();
    if (grp == 0) {
        float ts = 0.f, tss = 0.f;
#pragma unroll
        for (int i = 0; i < 8; i++) { ts += sh_s[i][lane32]; tss += sh_q[i][lane32]; }
        part[(2 * slice + 0) * DMODEL + col] = ts;
        part[(2 * slice + 1) * DMODEL + col] = tss;
    }
}

__global__ void __launch_bounds__(256)
bn_final_kernel(const float* __restrict__ part,
                const float* __restrict__ gamma, const float* __restrict__ beta,
                float* __restrict__ scale, float* __restrict__ shift)
{
    const int col = blockIdx.x * 256 + threadIdx.x;
    float s = 0.f, ss = 0.f;
#pragma unroll
    for (int i = 0; i < 8; i++) {
        s  += part[(2 * i + 0) * DMODEL + col];
        ss += part[(2 * i + 1) * DMODEL + col];
    }
    float mean = s * (1.0f / N_TOK);
    float var = ss * (1.0f / N_TOK) - mean * mean;
    float rstd = rsqrtf(var + 1e-5f);
    float sc = gamma[col] * rstd;
    scale[col] = sc;
    shift[col] = beta[col] - mean * sc;
}

__global__ void __launch_bounds__(256)
normalize_kernel(float* __restrict__ q,
                 const float* __restrict__ scale, const float* __restrict__ shift)
{
    int i = blockIdx.x * blockDim.x + threadIdx.x;
    float4* q4 = reinterpret_cast<float4*>(q);
    float4 v = q4[i];
    int c = (i * 4) & (DMODEL - 1);
    v.x = v.x * scale[c + 0] + shift[c + 0];
    v.y = v.y * scale[c + 1] + shift[c + 1];
    v.z = v.z * scale[c + 2] + shift[c + 2];
    v.w = v.w * scale[c + 3] + shift[c + 3];
    q4[i] = v;
}

// ---------------- warp-collective top-16 of 128 values ----------------
__device__ __forceinline__ void warp_top16(const float* __restrict__ row,
                                           float* __restrict__ ov, int* __restrict__ oi,
                                           int lane)
{
    float v0 = row[lane], v1 = row[lane + 32], v2 = row[lane + 64], v3 = row[lane + 96];
#pragma unroll 1
    for (int it = 0; it < 16; it++) {
        float bv = v0; int bu = 0;
        if (v1 > bv) { bv = v1; bu = 1; }
        if (v2 > bv) { bv = v2; bu = 2; }
        if (v3 > bv) { bv = v3; bu = 3; }
        int bidx = lane + (bu << 5);
#pragma unroll
        for (int off = 16; off; off >>= 1) {
            float ovv = __shfl_down_sync(0xffffffffu, bv, off);
            int oii = __shfl_down_sync(0xffffffffu, bidx, off);
            if (ovv > bv) { bv = ovv; bidx = oii; }
        }
        bv = __shfl_sync(0xffffffffu, bv, 0);
        bidx = __shfl_sync(0xffffffffu, bidx, 0);
        if (lane == 0) { ov[it] = bv; oi[it] = bidx; }
        if ((bidx & 31) == lane) {
            int u = bidx >> 5;
            if (u == 0) v0 = NEG_INF;
            else if (u == 1) v1 = NEG_INF;
            else if (u == 2) v2 = NEG_INF;
            else v3 = NEG_INF;
        }
    }
}

__global__ void __launch_bounds__(256)
topk_kernel(const float* __restrict__ s1, const float* __restrict__ s2,
            float* __restrict__ probs, int* __restrict__ eidx)
{
    const int wid = threadIdx.x >> 5;
    const int lane = threadIdx.x & 31;
    const int row = blockIdx.x * 8 + wid;
    __shared__ float tv1[8][16], tv2[8][16];
    __shared__ int ti1[8][16], ti2[8][16];

    warp_top16(s1 + (size_t)row * NSUB, tv1[wid], ti1[wid], lane);
    warp_top16(s2 + (size_t)row * NSUB, tv2[wid], ti2[wid], lane);
    __syncwarp();

    float cv[8];
#pragma unroll
    for (int t = 0; t < 8; t++) {
        int c = lane * 8 + t;
        cv[t] = tv1[wid][c >> 4] + tv2[wid][c & 15];
    }
    float fv[8]; int fi[8];
#pragma unroll 1
    for (int it = 0; it < 8; it++) {
        float bv = cv[0]; int bt = 0;
#pragma unroll
        for (int t = 1; t < 8; t++) if (cv[t] > bv) { bv = cv[t]; bt = t; }
        int bidx = lane * 8 + bt;
#pragma unroll
        for (int off = 16; off; off >>= 1) {
            float ovv = __shfl_down_sync(0xffffffffu, bv, off);
            int oii = __shfl_down_sync(0xffffffffu, bidx, off);
            if (ovv > bv) { bv = ovv; bidx = oii; }
        }
        bv = __shfl_sync(0xffffffffu, bv, 0);
        bidx = __shfl_sync(0xffffffffu, bidx, 0);
        fv[it] = bv; fi[it] = bidx;
        if ((bidx >> 3) == lane) cv[bidx & 7] = NEG_INF;
    }

    if (lane < 8) {
        float m = fv[0];
        float sum = 0.f;
#pragma unroll
        for (int i = 0; i < 8; i++) sum += expf(fv[i] - m);
        float p = expf(fv[lane] - m) / sum;
        int c = fi[lane];
        int i1 = ti1[wid][c >> 4];
        int i2 = ti2[wid][c & 15];
        probs[(size_t)row * 8 + lane] = p;
        eidx[(size_t)row * 8 + lane] = i1 * NSUB + i2;
    }
}

// ---------------- MoE per-token: warp-per-expert, sync-free mainloop ----------------
__global__ void __launch_bounds__(256)
moe_kernel(const float* __restrict__ xproj, const float* __restrict__ Hall,
           const float* __restrict__ probs, const int* __restrict__ eidx,
           float* __restrict__ accb)
{
    const int n = blockIdx.x;
    const int t = threadIdx.x;
    const int lane = t & 31, w = t >> 5;
    __shared__ float part[8][DHIDDEN];

    float xpr[16];
#pragma unroll
    for (int j = 0; j < 16; j++)
        xpr[j] = xproj[(size_t)n * DHIDDEN + j * 32 + lane];

    float pa[16];
#pragma unroll
    for (int j = 0; j < 16; j++) pa[j] = 0.f;

#pragma unroll
    for (int je = 0; je < 4; je++) {
        const int s = w * 4 + je;
        const int e = eidx[n * 32 + s];
        const float* H = Hall + (size_t)e * DHIDDEN;
        float h[16];
#pragma unroll
        for (int j = 0; j < 16; j++) h[j] = H[j * 32 + lane];
        float dot = 0.f;
#pragma unroll
        for (int j = 0; j < 16; j++) dot = fmaf(xpr[j], h[j], dot);
#pragma unroll
        for (int off = 16; off; off >>= 1)
            dot += __shfl_xor_sync(0xffffffffu, dot, off);
        const float act = gelu_exact(dot) * probs[n * 32 + s];
#pragma unroll
        for (int j = 0; j < 16; j++) pa[j] = fmaf(act, h[j], pa[j]);
    }
#pragma unroll
    for (int j = 0; j < 16; j++) part[w][j * 32 + lane] = pa[j];
    __syncthreads();

    float a0 = 0.f, a1 = 0.f;
#pragma unroll
    for (int w2 = 0; w2 < 8; w2++) {
        a0 += part[w2][t];
        a1 += part[w2][t + 256];
    }
    accb[(size_t)n * DHIDDEN + t] = a0;
    accb[(size_t)n * DHIDDEN + 256 + t] = a1;
}

// ---------------- host launch ----------------
extern "C" void kernel_launch(void* const* d_in, const int* in_sizes, int n_in,
                              void* d_out, int out_size)
{
    const float* x       = (const float*)d_in[0];
    const float* Wq      = (const float*)d_in[1];
    const float* bq      = (const float*)d_in[2];
    const float* gamma   = (const float*)d_in[3];
    const float* beta    = (const float*)d_in[4];
    const float* sk1     = (const float*)d_in[5];
    const float* sk2     = (const float*)d_in[6];
    const float* latents = (const float*)d_in[7];
    const float* W1      = (const float*)d_in[8];
    const float* W2      = (const float*)d_in[9];
    float* out = (float*)d_out;

    void *pq, *ps1, *ps2, *psc, *psh, *pbp, *pH, *pxp, *pacc, *ppr, *pei, *pw1t, *pwvt;
    cudaGetSymbolAddress(&pq, g_q);
    cudaGetSymbolAddress(&ps1, g_s1);
    cudaGetSymbolAddress(&ps2, g_s2);
    cudaGetSymbolAddress(&psc, g_scale);
    cudaGetSymbolAddress(&psh, g_shift);
    cudaGetSymbolAddress(&pbp, g_bnpart);
    cudaGetSymbolAddress(&pH, g_Hall);
    cudaGetSymbolAddress(&pxp, g_xproj);
    cudaGetSymbolAddress(&pacc, g_acc);
    cudaGetSymbolAddress(&ppr, g_probs);
    cudaGetSymbolAddress(&pei, g_eidx);
    cudaGetSymbolAddress(&pw1t, g_W1T);
    cudaGetSymbolAddress(&pwvt, g_WvT);

    float* q_buf   = (float*)pq;
    float* s1_buf  = (float*)ps1;
    float* s2_buf  = (float*)ps2;
    float* sc_buf  = (float*)psc;
    float* sh_buf  = (float*)psh;
    float* bp_buf  = (float*)pbp;
    float* H_buf   = (float*)pH;
    float* xp_buf  = (float*)pxp;
    float* acc_buf = (float*)pacc;
    float* pr_buf  = (float*)ppr;
    int*   ei_buf  = (int*)pei;
    float* w1t_buf = (float*)pw1t;
    float* wvt_buf = (float*)pwvt;

    cudaFuncSetAttribute(fp16_gemm, cudaFuncAttributeMaxDynamicSharedMemorySize, GEMM4_SMEM);
    cudaFuncSetAttribute(hp1_gemm<0>, cudaFuncAttributeMaxDynamicSharedMemorySize, GEMM1_SMEM);
    cudaFuncSetAttribute(hp1_gemm<1>, cudaFuncAttributeMaxDynamicSharedMemorySize, GEMM1_SMEM);

    const dim3 blk(256);
    const dim3 tblk(32, 8);

    transpose_kernel<<<dim3(DHIDDEN / 32, DLATENT / 32), tblk>>>(W1, DHIDDEN, DLATENT, w1t_buf);
    transpose_kernel<<<dim3(DMODEL / 32, DHIDDEN / 32), tblk>>>(W2 + DMODEL, 2 * DMODEL, DHIDDEN, wvt_buf);

    // 1) q = x @ Wq^T + bq   (fp16x3)
    fp16_gemm<<<dim3(DMODEL / 128, N_TOK / 128), blk, GEMM4_SMEM>>>(
        x, DMODEL, Wq, DMODEL, q_buf, DMODEL, DMODEL, bq);

    // 2) batchnorm stats
    bn_part_kernel<<<dim3(DMODEL / 32, 8), blk>>>(q_buf, bp_buf);
    bn_final_kernel<<<DMODEL / 256, blk>>>(bp_buf, gamma, beta, sc_buf, sh_buf);

    // H_all = gelu(latents @ W1T^T)   (fp16x1, independent of scoring chain)
    hp1_gemm<1><<<dim3(DHIDDEN / 128, NEXPERTS / 128), blk, GEMM1_SMEM>>>(
        latents, DLATENT, w1t_buf, DLATENT, H_buf, DHIDDEN, DLATENT, nullptr, 1.0f);

    // 3) normalize
    normalize_kernel<<<(N_TOK * DMODEL / 4) / 256, blk>>>(q_buf, sc_buf, sh_buf);

    // 4) s1/s2 (fp16x3)
    fp16_gemm<<<dim3(1, (N_TOK * NHEADS) / 128), blk, GEMM4_SMEM>>>(
        q_buf, DQUERY, sk1, NSUB, s1_buf, NSUB, NSUB, nullptr);
    fp16_gemm<<<dim3(1, (N_TOK * NHEADS) / 128), blk, GEMM4_SMEM>>>(
        q_buf + 128, DQUERY, sk2, NSUB, s2_buf, NSUB, NSUB, nullptr);

    // 5) two-level top-k
    topk_kernel<<<(N_TOK * NHEADS) / 8, blk>>>(s1_buf, s2_buf, pr_buf, ei_buf);

    // 7) x_proj = x @ W2[:, :D]^T   (fp16x1)
    hp1_gemm<0><<<dim3(DHIDDEN / 128, N_TOK / 128), blk, GEMM1_SMEM>>>(
        x, DMODEL, W2, 2 * DMODEL, xp_buf, DHIDDEN, DMODEL, nullptr, 1.0f);

    // 8) MoE gather / act / accumulate
    moe_kernel<<<N_TOK, blk>>>(xp_buf, H_buf, pr_buf, ei_buf, acc_buf);

    // 9) out = acc @ WvT^T / 4   (fp16x1)
    hp1_gemm<0><<<dim3(DMODEL / 128, N_TOK / 128), blk, GEMM1_SMEM>>>(
        acc_buf, DHIDDEN, wvt_buf, DHIDDEN, out, DMODEL, DHIDDEN, nullptr, 0.25f);
}

// round 16
// speedup vs baseline: 1.9354x; 1.1643x over previous
#include <cuda_runtime.h>
#include <cuda_fp16.h>
#include <math.h>
#include <stdint.h>

#define N_TOK        8192
#define DMODEL       1024
#define DQUERY       256
#define NHEADS       4
#define NSUB         128
#define TOPK         8
#define DLATENT      256
#define DHIDDEN      512
#define NEXPERTS     16384
#define NEG_INF      (-1.0e38f)

// ---------------- scratch (device globals; no allocation allowed) ----------------
__device__ float g_q[N_TOK * DMODEL];
__device__ float g_s1[N_TOK * NHEADS * NSUB];
__device__ float g_s2[N_TOK * NHEADS * NSUB];
__device__ float g_scale[DMODEL];
__device__ float g_shift[DMODEL];
__device__ float g_bnpart[16 * DMODEL];
__device__ float g_Hall[NEXPERTS * DHIDDEN];
__device__ float g_xproj[N_TOK * DHIDDEN];
__device__ float g_probs[N_TOK * NHEADS * TOPK];
__device__ int   g_eidx[N_TOK * NHEADS * TOPK];
// fp16 operand arrays (hi/lo pairs are byte-neutral vs fp32)
__device__ __align__(16) __half g_xh[N_TOK * DMODEL];
__device__ __align__(16) __half g_xl[N_TOK * DMODEL];
__device__ __align__(16) __half g_wqh[DMODEL * DMODEL];
__device__ __align__(16) __half g_wql[DMODEL * DMODEL];
__device__ __align__(16) __half g_qh[N_TOK * DMODEL];   // FIXED: full normalized q (all heads)
__device__ __align__(16) __half g_ql[N_TOK * DMODEL];   // FIXED
__device__ __align__(16) __half g_sk1h[NSUB * 128];
__device__ __align__(16) __half g_sk1l[NSUB * 128];
__device__ __align__(16) __half g_sk2h[NSUB * 128];
__device__ __align__(16) __half g_sk2l[NSUB * 128];
__device__ __align__(16) __half g_lath[NEXPERTS * DLATENT];
__device__ __align__(16) __half g_w1th[DHIDDEN * DLATENT];
__device__ __align__(16) __half g_w2h[DHIDDEN * DMODEL];
__device__ __align__(16) __half g_wvth[DMODEL * DHIDDEN];
__device__ __align__(16) __half g_acch[N_TOK * DHIDDEN];

__device__ __forceinline__ float gelu_exact(float x) {
    return 0.5f * x * (1.0f + erff(x * 0.70710678118654752f));
}
__device__ __forceinline__ uint32_t smem_u32(const void* p) {
    uint32_t a;
    asm("{ .reg .u64 t; cvta.to.shared.u64 t, %1; cvt.u32.u64 %0, t; }" : "=r"(a) : "l"(p));
    return a;
}
__device__ __forceinline__ uint32_t sw128(uint32_t o) { return o ^ ((o >> 3) & 0x70); }

__device__ __forceinline__ void ldsm_x4(uint32_t* r, uint32_t addr) {
    asm volatile("ldmatrix.sync.aligned.m8n8.x4.shared.b16 {%0,%1,%2,%3}, [%4];"
                 : "=r"(r[0]), "=r"(r[1]), "=r"(r[2]), "=r"(r[3]) : "r"(addr));
}
__device__ __forceinline__ void mma16816h(float* d, const uint32_t* a, const uint32_t* b) {
    asm volatile(
        "mma.sync.aligned.m16n8k16.row.col.f32.f16.f16.f32 "
        "{%0,%1,%2,%3}, {%4,%5,%6,%7}, {%8,%9}, {%0,%1,%2,%3};"
        : "+f"(d[0]), "+f"(d[1]), "+f"(d[2]), "+f"(d[3])
        : "r"(a[0]), "r"(a[1]), "r"(a[2]), "r"(a[3]), "r"(b[0]), "r"(b[1]));
}

// ---------------- cp.async helpers ----------------
__device__ __forceinline__ void cp16(uint32_t dst, const void* src) {
    asm volatile("cp.async.cg.shared.global [%0], [%1], 16;"
                 :: "r"(dst), "l"(__cvta_generic_to_global(src)));
}
__device__ __forceinline__ void cp_commit() {
    asm volatile("cp.async.commit_group;" ::: "memory");
}
__device__ __forceinline__ void cp_wait0() {
    asm volatile("cp.async.wait_group 0;" ::: "memory");
}

#define TILE_BYTES 16384
#define STAGE4_BYTES (4 * TILE_BYTES)
#define GEMM4_SMEM  (2 * STAGE4_BYTES + 1024)
#define STAGE1_BYTES (2 * TILE_BYTES)
#define GEMM1_SMEM  (2 * STAGE1_BYTES + 1024)

// fp16 tile (128 rows x 64 halves = 128B/row), SW128-swizzled, via cp.async
__device__ __forceinline__ void cp_tile_h(uint32_t sm, const __half* __restrict__ src,
                                          int ld, int tid)
{
    const int row = tid >> 1;
    const int cb = (tid & 1) * 4;
    const __half* s = src + (size_t)row * ld + cb * 8;
#pragma unroll
    for (int j = 0; j < 4; j++) {
        uint32_t off = sw128((uint32_t)(row * 128 + (cb + j) * 16));
        cp16(sm + off, s + j * 8);
    }
}

// ================================================================
// fp16x3 HMMA GEMM (scoring): A,B pre-split hi/lo fp16 globals
// per-accumulator order: AhBh, AlBh, AhBl (identical to round 14)
// ================================================================
__global__ void __launch_bounds__(256, 1)
fp16_gemm(const __half* __restrict__ Ah0, const __half* __restrict__ Al0, int lda,
          const __half* __restrict__ Bh0, const __half* __restrict__ Bl0, int ldb,
          float* __restrict__ C, int ldc, int K,
          const float* __restrict__ bias)
{
    extern __shared__ char dsm[];
    const uint32_t raw = smem_u32(dsm);
    const uint32_t base = (raw + 1023) & ~1023u;

    const int tid  = threadIdx.x;
    const int lane = tid & 31;
    const int wid  = tid >> 5;
    const int wm = wid & 3;
    const int wn = wid >> 2;
    const int bm = blockIdx.y * 128;
    const int bn = blockIdx.x * 128;

    const __half* Ah = Ah0 + (size_t)bm * lda;
    const __half* Al = Al0 + (size_t)bm * lda;
    const __half* Bh = Bh0 + (size_t)bn * ldb;
    const __half* Bl = Bl0 + (size_t)bn * ldb;
    const int nk = K >> 6;

    {
        const uint32_t sb = base;
        cp_tile_h(sb,                  Ah, lda, tid);
        cp_tile_h(sb +     TILE_BYTES, Al, lda, tid);
        cp_tile_h(sb + 2 * TILE_BYTES, Bh, ldb, tid);
        cp_tile_h(sb + 3 * TILE_BYTES, Bl, ldb, tid);
        cp_commit();
        cp_wait0();
        __syncthreads();
    }

    float acc[2][8][4];
#pragma unroll
    for (int i = 0; i < 2; i++)
#pragma unroll
        for (int j = 0; j < 8; j++)
#pragma unroll
            for (int t = 0; t < 4; t++) acc[i][j][t] = 0.f;

    const int a_row = wm * 32 + (lane & 15);
    const int a_kb0 = (lane >> 4) << 4;
    const int b_row0 = wn * 64 + (lane & 7) + ((lane >> 4) << 3);
    const int b_kb0 = ((lane >> 3) & 1) << 4;

    for (int kc = 0; kc < nk; kc++) {
        const int cur = kc & 1;
        const bool more = (kc + 1 < nk);
        if (more) {
            const uint32_t sb = base + (cur ^ 1) * STAGE4_BYTES;
            cp_tile_h(sb,                  Ah + (kc + 1) * 64, lda, tid);
            cp_tile_h(sb +     TILE_BYTES, Al + (kc + 1) * 64, lda, tid);
            cp_tile_h(sb + 2 * TILE_BYTES, Bh + (kc + 1) * 64, ldb, tid);
            cp_tile_h(sb + 3 * TILE_BYTES, Bl + (kc + 1) * 64, ldb, tid);
            cp_commit();
        }
        const uint32_t sb = base + cur * STAGE4_BYTES;
#pragma unroll
        for (int ks = 0; ks < 4; ks++) {
            uint32_t Afh[2][4], Afl[2][4];
#pragma unroll
            for (int mf = 0; mf < 2; mf++) {
                uint32_t off = sw128((uint32_t)((a_row + mf * 16) * 128 + ks * 32 + a_kb0));
                ldsm_x4(Afh[mf], sb + off);
                ldsm_x4(Afl[mf], sb + TILE_BYTES + off);
            }
            uint32_t Bfh[4][4], Bfl[4][4];
#pragma unroll
            for (int nf2 = 0; nf2 < 4; nf2++) {
                uint32_t off = sw128((uint32_t)((b_row0 + nf2 * 16) * 128 + ks * 32 + b_kb0));
                ldsm_x4(Bfh[nf2], sb + 2 * TILE_BYTES + off);
                ldsm_x4(Bfl[nf2], sb + 3 * TILE_BYTES + off);
            }
#pragma unroll
            for (int nf2 = 0; nf2 < 4; nf2++)
#pragma unroll
                for (int mf = 0; mf < 2; mf++) {
                    mma16816h(acc[mf][nf2 * 2 + 0], Afh[mf], Bfh[nf2] + 0);
                    mma16816h(acc[mf][nf2 * 2 + 1], Afh[mf], Bfh[nf2] + 2);
                }
#pragma unroll
            for (int nf2 = 0; nf2 < 4; nf2++)
#pragma unroll
                for (int mf = 0; mf < 2; mf++) {
                    mma16816h(acc[mf][nf2 * 2 + 0], Afl[mf], Bfh[nf2] + 0);
                    mma16816h(acc[mf][nf2 * 2 + 1], Afl[mf], Bfh[nf2] + 2);
                }
#pragma unroll
            for (int nf2 = 0; nf2 < 4; nf2++)
#pragma unroll
                for (int mf = 0; mf < 2; mf++) {
                    mma16816h(acc[mf][nf2 * 2 + 0], Afh[mf], Bfl[nf2] + 0);
                    mma16816h(acc[mf][nf2 * 2 + 1], Afh[mf], Bfl[nf2] + 2);
                }
        }
        if (more) cp_wait0();
        __syncthreads();
    }

#pragma unroll
    for (int mf = 0; mf < 2; mf++) {
        const int row = bm + wm * 32 + mf * 16 + (lane >> 2);
#pragma unroll
        for (int nf = 0; nf < 8; nf++) {
            const int col = bn + wn * 64 + nf * 8 + (lane & 3) * 2;
            float b0 = 0.f, b1 = 0.f;
            if (bias) { b0 = bias[col]; b1 = bias[col + 1]; }
            *reinterpret_cast<float2*>(C + (size_t)row * ldc + col) =
                make_float2(acc[mf][nf][0] + b0, acc[mf][nf][1] + b1);
            *reinterpret_cast<float2*>(C + (size_t)(row + 8) * ldc + col) =
                make_float2(acc[mf][nf][2] + b0, acc[mf][nf][3] + b1);
        }
    }
}

// ================================================================
// fp16x1 HMMA GEMM (continuous): pre-rounded fp16 A,B; 2 CTAs/SM
// ================================================================
template<int ACT>   // 0 = none, 1 = gelu
__global__ void __launch_bounds__(256, 2)
hp1_gemm(const __half* __restrict__ A0, int lda,
         const __half* __restrict__ B0, int ldb,
         float* __restrict__ C, int ldc, int K,
         const float* __restrict__ bias, float scale)
{
    extern __shared__ char dsm[];
    const uint32_t raw = smem_u32(dsm);
    const uint32_t base = (raw + 1023) & ~1023u;

    const int tid  = threadIdx.x;
    const int lane = tid & 31;
    const int wid  = tid >> 5;
    const int wm = wid & 3;
    const int wn = wid >> 2;
    const int bm = blockIdx.y * 128;
    const int bn = blockIdx.x * 128;

    const __half* Ap = A0 + (size_t)bm * lda;
    const __half* Bp = B0 + (size_t)bn * ldb;
    const int nk = K >> 6;

    {
        const uint32_t sb = base;
        cp_tile_h(sb,              Ap, lda, tid);
        cp_tile_h(sb + TILE_BYTES, Bp, ldb, tid);
        cp_commit();
        cp_wait0();
        __syncthreads();
    }

    float acc[2][8][4];
#pragma unroll
    for (int i = 0; i < 2; i++)
#pragma unroll
        for (int j = 0; j < 8; j++)
#pragma unroll
            for (int t = 0; t < 4; t++) acc[i][j][t] = 0.f;

    const int a_row = wm * 32 + (lane & 15);
    const int a_kb0 = (lane >> 4) << 4;
    const int b_row0 = wn * 64 + (lane & 7) + ((lane >> 4) << 3);
    const int b_kb0 = ((lane >> 3) & 1) << 4;

    for (int kc = 0; kc < nk; kc++) {
        const int cur = kc & 1;
        const bool more = (kc + 1 < nk);
        if (more) {
            const uint32_t sb = base + (cur ^ 1) * STAGE1_BYTES;
            cp_tile_h(sb,              Ap + (kc + 1) * 64, lda, tid);
            cp_tile_h(sb + TILE_BYTES, Bp + (kc + 1) * 64, ldb, tid);
            cp_commit();
        }
        const uint32_t sb = base + cur * STAGE1_BYTES;
#pragma unroll
        for (int ks = 0; ks < 4; ks++) {
            uint32_t Afh[2][4];
#pragma unroll
            for (int mf = 0; mf < 2; mf++) {
                uint32_t off = sw128((uint32_t)((a_row + mf * 16) * 128 + ks * 32 + a_kb0));
                ldsm_x4(Afh[mf], sb + off);
            }
            uint32_t Bfh[4][4];
#pragma unroll
            for (int nf2 = 0; nf2 < 4; nf2++) {
                uint32_t off = sw128((uint32_t)((b_row0 + nf2 * 16) * 128 + ks * 32 + b_kb0));
                ldsm_x4(Bfh[nf2], sb + TILE_BYTES + off);
            }
#pragma unroll
            for (int nf2 = 0; nf2 < 4; nf2++)
#pragma unroll
                for (int mf = 0; mf < 2; mf++) {
                    mma16816h(acc[mf][nf2 * 2 + 0], Afh[mf], Bfh[nf2] + 0);
                    mma16816h(acc[mf][nf2 * 2 + 1], Afh[mf], Bfh[nf2] + 2);
                }
        }
        if (more) cp_wait0();
        __syncthreads();
    }

#pragma unroll
    for (int mf = 0; mf < 2; mf++) {
        const int row = bm + wm * 32 + mf * 16 + (lane >> 2);
#pragma unroll
        for (int nf = 0; nf < 8; nf++) {
            const int col = bn + wn * 64 + nf * 8 + (lane & 3) * 2;
            float b0 = 0.f, b1 = 0.f;
            if (bias) { b0 = bias[col]; b1 = bias[col + 1]; }
            float v0 = acc[mf][nf][0] + b0;
            float v1 = acc[mf][nf][1] + b1;
            float v2 = acc[mf][nf][2] + b0;
            float v3 = acc[mf][nf][3] + b1;
            if (ACT == 1) {
                v0 = gelu_exact(v0); v1 = gelu_exact(v1);
                v2 = gelu_exact(v2); v3 = gelu_exact(v3);
            }
            v0 *= scale; v1 *= scale; v2 *= scale; v3 *= scale;
            *reinterpret_cast<float2*>(C + (size_t)row * ldc + col) = make_float2(v0, v1);
            *reinterpret_cast<float2*>(C + (size_t)(row + 8) * ldc + col) = make_float2(v2, v3);
        }
    }
}

// ================================================================
// operand prep kernels
// ================================================================
__device__ __forceinline__ void pack_split4(float4 v, uint2& hp, uint2& lp)
{
    __half h0 = __float2half_rn(v.x);
    __half h1 = __float2half_rn(v.y);
    __half h2 = __float2half_rn(v.z);
    __half h3 = __float2half_rn(v.w);
    __half l0 = __float2half_rn(v.x - __half2float(h0));
    __half l1 = __float2half_rn(v.y - __half2float(h1));
    __half l2 = __float2half_rn(v.z - __half2float(h2));
    __half l3 = __float2half_rn(v.w - __half2float(h3));
    hp.x = ((uint32_t)__half_as_ushort(h1) << 16) | __half_as_ushort(h0);
    hp.y = ((uint32_t)__half_as_ushort(h3) << 16) | __half_as_ushort(h2);
    lp.x = ((uint32_t)__half_as_ushort(l1) << 16) | __half_as_ushort(l0);
    lp.y = ((uint32_t)__half_as_ushort(l3) << 16) | __half_as_ushort(l2);
}
__device__ __forceinline__ uint2 pack_round4(float4 v)
{
    uint2 h;
    h.x = ((uint32_t)__half_as_ushort(__float2half_rn(v.y)) << 16)
        | __half_as_ushort(__float2half_rn(v.x));
    h.y = ((uint32_t)__half_as_ushort(__float2half_rn(v.w)) << 16)
        | __half_as_ushort(__float2half_rn(v.z));
    return h;
}

__global__ void __launch_bounds__(256)
split_fp16_kernel(const float* __restrict__ src,
                  __half* __restrict__ hi, __half* __restrict__ lo)
{
    const int i = blockIdx.x * 256 + threadIdx.x;
    float4 v = reinterpret_cast<const float4*>(src)[i];
    uint2 hp, lp;
    pack_split4(v, hp, lp);
    reinterpret_cast<uint2*>(hi)[i] = hp;
    reinterpret_cast<uint2*>(lo)[i] = lp;
}

__global__ void __launch_bounds__(256)
round_fp16_kernel(const float* __restrict__ src, __half* __restrict__ hi)
{
    const int i = blockIdx.x * 256 + threadIdx.x;
    reinterpret_cast<uint2*>(hi)[i] =
        pack_round4(reinterpret_cast<const float4*>(src)[i]);
}

// strided source (row stride sld, cols4*4 cols per row) -> dense fp16
__global__ void __launch_bounds__(256)
round_fp16_strided(const float* __restrict__ src, int sld, int cols4,
                   __half* __restrict__ hi)
{
    const int i = blockIdx.x * 256 + threadIdx.x;
    const int row = i / cols4, c4 = i % cols4;
    float4 v = *reinterpret_cast<const float4*>(src + (size_t)row * sld + c4 * 4);
    reinterpret_cast<uint2*>(hi)[i] = pack_round4(v);
}

// transpose fp32 -> fp16: dst[c][r] = (half)src[r][c]
__global__ void __launch_bounds__(256)
transpose_h_kernel(const float* __restrict__ src, int sld, int rows,
                   __half* __restrict__ dst)
{
    __shared__ float t[32][33];
    const int bx = blockIdx.x * 32, by = blockIdx.y * 32;
    int x = bx + threadIdx.x, y = by + threadIdx.y;
#pragma unroll
    for (int i = 0; i < 32; i += 8)
        t[threadIdx.y + i][threadIdx.x] = src[(size_t)(y + i) * sld + x];
    __syncthreads();
    x = by + threadIdx.x; y = bx + threadIdx.y;
#pragma unroll
    for (int i = 0; i < 32; i += 8)
        dst[(size_t)(y + i) * rows + x] = __float2half_rn(t[threadIdx.x][threadIdx.y + i]);
}

// ---------------- batchnorm: partial stats, then finalize ----------------
__global__ void __launch_bounds__(256)
bn_part_kernel(const float* __restrict__ q, float* __restrict__ part)
{
    const int lane32 = threadIdx.x & 31;
    const int grp = threadIdx.x >> 5;
    const int col = blockIdx.x * 32 + lane32;
    const int slice = blockIdx.y;
    const int r0 = slice * (N_TOK / 8);
    float s = 0.f, ss = 0.f;
    for (int r = grp; r < N_TOK / 8; r += 8) {
        float v = q[(size_t)(r0 + r) * DMODEL + col];
        s += v;
        ss += v * v;
    }
    __shared__ float sh_s[8][33], sh_q[8][33];
    sh_s[grp][lane32] = s;
    sh_q[grp][lane32] = ss;
    __syncthreads();
    if (grp == 0) {
        float ts = 0.f, tss = 0.f;
#pragma unroll
        for (int i = 0; i < 8; i++) { ts += sh_s[i][lane32]; tss += sh_q[i][lane32]; }
        part[(2 * slice + 0) * DMODEL + col] = ts;
        part[(2 * slice + 1) * DMODEL + col] = tss;
    }
}

__global__ void __launch_bounds__(256)
bn_final_kernel(const float* __restrict__ part,
                const float* __restrict__ gamma, const float* __restrict__ beta,
                float* __restrict__ scale, float* __restrict__ shift)
{
    const int col = blockIdx.x * 256 + threadIdx.x;
    float s = 0.f, ss = 0.f;
#pragma unroll
    for (int i = 0; i < 8; i++) {
        s  += part[(2 * i + 0) * DMODEL + col];
        ss += part[(2 * i + 1) * DMODEL + col];
    }
    float mean = s * (1.0f / N_TOK);
    float var = ss * (1.0f / N_TOK) - mean * mean;
    float rstd = rsqrtf(var + 1e-5f);
    float sc = gamma[col] * rstd;
    scale[col] = sc;
    shift[col] = beta[col] - mean * sc;
}

// normalize + fp16 hi/lo split (byte-neutral)
__global__ void __launch_bounds__(256)
normalize_split_kernel(const float* __restrict__ q,
                       const float* __restrict__ scale, const float* __restrict__ shift,
                       __half* __restrict__ qh, __half* __restrict__ ql)
{
    int i = blockIdx.x * blockDim.x + threadIdx.x;
    float4 v = reinterpret_cast<const float4*>(q)[i];
    int c = (i * 4) & (DMODEL - 1);
    v.x = v.x * scale[c + 0] + shift[c + 0];
    v.y = v.y * scale[c + 1] + shift[c + 1];
    v.z = v.z * scale[c + 2] + shift[c + 2];
    v.w = v.w * scale[c + 3] + shift[c + 3];
    uint2 hp, lp;
    pack_split4(v, hp, lp);
    reinterpret_cast<uint2*>(qh)[i] = hp;
    reinterpret_cast<uint2*>(ql)[i] = lp;
}

// ---------------- warp-collective top-16 of 128 values ----------------
__device__ __forceinline__ void warp_top16(const float* __restrict__ row,
                                           float* __restrict__ ov, int* __restrict__ oi,
                                           int lane)
{
    float v0 = row[lane], v1 = row[lane + 32], v2 = row[lane + 64], v3 = row[lane + 96];
#pragma unroll 1
    for (int it = 0; it < 16; it++) {
        float bv = v0; int bu = 0;
        if (v1 > bv) { bv = v1; bu = 1; }
        if (v2 > bv) { bv = v2; bu = 2; }
        if (v3 > bv) { bv = v3; bu = 3; }
        int bidx = lane + (bu << 5);
#pragma unroll
        for (int off = 16; off; off >>= 1) {
            float ovv = __shfl_down_sync(0xffffffffu, bv, off);
            int oii = __shfl_down_sync(0xffffffffu, bidx, off);
            if (ovv > bv) { bv = ovv; bidx = oii; }
        }
        bv = __shfl_sync(0xffffffffu, bv, 0);
        bidx = __shfl_sync(0xffffffffu, bidx, 0);
        if (lane == 0) { ov[it] = bv; oi[it] = bidx; }
        if ((bidx & 31) == lane) {
            int u = bidx >> 5;
            if (u == 0) v0 = NEG_INF;
            else if (u == 1) v1 = NEG_INF;
            else if (u == 2) v2 = NEG_INF;
            else v3 = NEG_INF;
        }
    }
}

__global__ void __launch_bounds__(256)
topk_kernel(const float* __restrict__ s1, const float* __restrict__ s2,
            float* __restrict__ probs, int* __restrict__ eidx)
{
    const int wid = threadIdx.x >> 5;
    const int lane = threadIdx.x & 31;
    const int row = blockIdx.x * 8 + wid;
    __shared__ float tv1[8][16], tv2[8][16];
    __shared__ int ti1[8][16], ti2[8][16];

    warp_top16(s1 + (size_t)row * NSUB, tv1[wid], ti1[wid], lane);
    warp_top16(s2 + (size_t)row * NSUB, tv2[wid], ti2[wid], lane);
    __syncwarp();

    float cv[8];
#pragma unroll
    for (int t = 0; t < 8; t++) {
        int c = lane * 8 + t;
        cv[t] = tv1[wid][c >> 4] + tv2[wid][c & 15];
    }
    float fv[8]; int fi[8];
#pragma unroll 1
    for (int it = 0; it < 8; it++) {
        float bv = cv[0]; int bt = 0;
#pragma unroll
        for (int t = 1; t < 8; t++) if (cv[t] > bv) { bv = cv[t]; bt = t; }
        int bidx = lane * 8 + bt;
#pragma unroll
        for (int off = 16; off; off >>= 1) {
            float ovv = __shfl_down_sync(0xffffffffu, bv, off);
            int oii = __shfl_down_sync(0xffffffffu, bidx, off);
            if (ovv > bv) { bv = ovv; bidx = oii; }
        }
        bv = __shfl_sync(0xffffffffu, bv, 0);
        bidx = __shfl_sync(0xffffffffu, bidx, 0);
        fv[it] = bv; fi[it] = bidx;
        if ((bidx >> 3) == lane) cv[bidx & 7] = NEG_INF;
    }

    if (lane < 8) {
        float m = fv[0];
        float sum = 0.f;
#pragma unroll
        for (int i = 0; i < 8; i++) sum += expf(fv[i] - m);
        float p = expf(fv[lane] - m) / sum;
        int c = fi[lane];
        int i1 = ti1[wid][c >> 4];
        int i2 = ti2[wid][c & 15];
        probs[(size_t)row * 8 + lane] = p;
        eidx[(size_t)row * 8 + lane] = i1 * NSUB + i2;
    }
}

// ---------------- MoE per-token: warp-per-expert; writes acc as fp16 ----------------
__global__ void __launch_bounds__(256)
moe_kernel(const float* __restrict__ xproj, const float* __restrict__ Hall,
           const float* __restrict__ probs, const int* __restrict__ eidx,
           __half* __restrict__ acch)
{
    const int n = blockIdx.x;
    const int t = threadIdx.x;
    const int lane = t & 31, w = t >> 5;
    __shared__ float part[8][DHIDDEN];

    float xpr[16];
#pragma unroll
    for (int j = 0; j < 16; j++)
        xpr[j] = xproj[(size_t)n * DHIDDEN + j * 32 + lane];

    float pa[16];
#pragma unroll
    for (int j = 0; j < 16; j++) pa[j] = 0.f;

#pragma unroll
    for (int je = 0; je < 4; je++) {
        const int s = w * 4 + je;
        const int e = eidx[n * 32 + s];
        const float* H = Hall + (size_t)e * DHIDDEN;
        float h[16];
#pragma unroll
        for (int j = 0; j < 16; j++) h[j] = H[j * 32 + lane];
        float dot = 0.f;
#pragma unroll
        for (int j = 0; j < 16; j++) dot = fmaf(xpr[j], h[j], dot);
#pragma unroll
        for (int off = 16; off; off >>= 1)
            dot += __shfl_xor_sync(0xffffffffu, dot, off);
        const float act = gelu_exact(dot) * probs[n * 32 + s];
#pragma unroll
        for (int j = 0; j < 16; j++) pa[j] = fmaf(act, h[j], pa[j]);
    }
#pragma unroll
    for (int j = 0; j < 16; j++) part[w][j * 32 + lane] = pa[j];
    __syncthreads();

    float a0 = 0.f, a1 = 0.f;
#pragma unroll
    for (int w2 = 0; w2 < 8; w2++) {
        a0 += part[w2][t];
        a1 += part[w2][t + 256];
    }
    acch[(size_t)n * DHIDDEN + t]       = __float2half_rn(a0);
    acch[(size_t)n * DHIDDEN + 256 + t] = __float2half_rn(a1);
}

// ---------------- host launch ----------------
extern "C" void kernel_launch(void* const* d_in, const int* in_sizes, int n_in,
                              void* d_out, int out_size)
{
    const float* x       = (const float*)d_in[0];
    const float* Wq      = (const float*)d_in[1];
    const float* bq      = (const float*)d_in[2];
    const float* gamma   = (const float*)d_in[3];
    const float* beta    = (const float*)d_in[4];
    const float* sk1     = (const float*)d_in[5];
    const float* sk2     = (const float*)d_in[6];
    const float* latents = (const float*)d_in[7];
    const float* W1      = (const float*)d_in[8];
    const float* W2      = (const float*)d_in[9];
    float* out = (float*)d_out;

#define SYM(var, sym) void* p_##var; cudaGetSymbolAddress(&p_##var, sym);
    SYM(q, g_q) SYM(s1, g_s1) SYM(s2, g_s2)
    SYM(sc, g_scale) SYM(sh, g_shift) SYM(bp, g_bnpart)
    SYM(H, g_Hall) SYM(xp, g_xproj)
    SYM(pr, g_probs) SYM(ei, g_eidx)
    SYM(xh, g_xh) SYM(xl, g_xl)
    SYM(wqh, g_wqh) SYM(wql, g_wql)
    SYM(qh, g_qh) SYM(ql, g_ql)
    SYM(sk1h, g_sk1h) SYM(sk1l, g_sk1l) SYM(sk2h, g_sk2h) SYM(sk2l, g_sk2l)
    SYM(lath, g_lath) SYM(w1th, g_w1th) SYM(w2h, g_w2h)
    SYM(wvth, g_wvth) SYM(acch, g_acch)
#undef SYM

    cudaFuncSetAttribute(fp16_gemm, cudaFuncAttributeMaxDynamicSharedMemorySize, GEMM4_SMEM);
    cudaFuncSetAttribute(hp1_gemm<0>, cudaFuncAttributeMaxDynamicSharedMemorySize, GEMM1_SMEM);
    cudaFuncSetAttribute(hp1_gemm<1>, cudaFuncAttributeMaxDynamicSharedMemorySize, GEMM1_SMEM);

    const dim3 blk(256);
    const dim3 tblk(32, 8);

    // ---- operand prep (one-time per launch) ----
    split_fp16_kernel<<<(N_TOK * DMODEL / 4) / 256, blk>>>(x, (__half*)p_xh, (__half*)p_xl);
    split_fp16_kernel<<<(DMODEL * DMODEL / 4) / 256, blk>>>(Wq, (__half*)p_wqh, (__half*)p_wql);
    split_fp16_kernel<<<(NSUB * 128 / 4) / 256, blk>>>(sk1, (__half*)p_sk1h, (__half*)p_sk1l);
    split_fp16_kernel<<<(NSUB * 128 / 4) / 256, blk>>>(sk2, (__half*)p_sk2h, (__half*)p_sk2l);
    round_fp16_kernel<<<(NEXPERTS * DLATENT / 4) / 256, blk>>>(latents, (__half*)p_lath);
    round_fp16_strided<<<(DHIDDEN * DMODEL / 4) / 256, blk>>>(W2, 2 * DMODEL, DMODEL / 4, (__half*)p_w2h);
    transpose_h_kernel<<<dim3(DHIDDEN / 32, DLATENT / 32), tblk>>>(W1, DHIDDEN, DLATENT, (__half*)p_w1th);
    transpose_h_kernel<<<dim3(DMODEL / 32, DHIDDEN / 32), tblk>>>(W2 + DMODEL, 2 * DMODEL, DHIDDEN, (__half*)p_wvth);

    // 1) q = x @ Wq^T + bq   (fp16x3, cp.async)
    fp16_gemm<<<dim3(DMODEL / 128, N_TOK / 128), blk, GEMM4_SMEM>>>(
        (__half*)p_xh, (__half*)p_xl, DMODEL, (__half*)p_wqh, (__half*)p_wql, DMODEL,
        (float*)p_q, DMODEL, DMODEL, bq);

    // 2) batchnorm stats
    bn_part_kernel<<<dim3(DMODEL / 32, 8), blk>>>((float*)p_q, (float*)p_bp);
    bn_final_kernel<<<DMODEL / 256, blk>>>((float*)p_bp, gamma, beta, (float*)p_sc, (float*)p_sh);

    // H_all = gelu(latents @ W1T^T)   (fp16x1; independent chain)
    hp1_gemm<1><<<dim3(DHIDDEN / 128, NEXPERTS / 128), blk, GEMM1_SMEM>>>(
        (__half*)p_lath, DLATENT, (__half*)p_w1th, DLATENT,
        (float*)p_H, DHIDDEN, DLATENT, nullptr, 1.0f);

    // 3) normalize + split q -> qh/ql (full N_TOK x DMODEL)
    normalize_split_kernel<<<(N_TOK * DMODEL / 4) / 256, blk>>>(
        (float*)p_q, (float*)p_sc, (float*)p_sh, (__half*)p_qh, (__half*)p_ql);

    // 4) s1/s2 (fp16x3, cp.async); q viewed as 32768 rows x 256 (lda=DQUERY)
    fp16_gemm<<<dim3(1, (N_TOK * NHEADS) / 128), blk, GEMM4_SMEM>>>(
        (__half*)p_qh, (__half*)p_ql, DQUERY, (__half*)p_sk1h, (__half*)p_sk1l, NSUB,
        (float*)p_s1, NSUB, NSUB, nullptr);
    fp16_gemm<<<dim3(1, (N_TOK * NHEADS) / 128), blk, GEMM4_SMEM>>>(
        (__half*)p_qh + 128, (__half*)p_ql + 128, DQUERY, (__half*)p_sk2h, (__half*)p_sk2l, NSUB,
        (float*)p_s2, NSUB, NSUB, nullptr);

    // 5) two-level top-k
    topk_kernel<<<(N_TOK * NHEADS) / 8, blk>>>((float*)p_s1, (float*)p_s2, (float*)p_pr, (int*)p_ei);

    // 7) x_proj = x @ W2[:, :D]^T   (fp16x1)
    hp1_gemm<0><<<dim3(DHIDDEN / 128, N_TOK / 128), blk, GEMM1_SMEM>>>(
        (__half*)p_xh, DMODEL, (__half*)p_w2h, DMODEL,
        (float*)p_xp, DHIDDEN, DMODEL, nullptr, 1.0f);

    // 8) MoE gather / act / accumulate (writes acc fp16)
    moe_kernel<<<N_TOK, blk>>>((float*)p_xp, (float*)p_H, (float*)p_pr, (int*)p_ei,
                               (__half*)p_acch);

    // 9) out = acc @ WvT^T / 4   (fp16x1)
    hp1_gemm<0><<<dim3(DMODEL / 128, N_TOK / 128), blk, GEMM1_SMEM>>>(
        (__half*)p_acch, DHIDDEN, (__half*)p_wvth, DHIDDEN,
        out, DMODEL, DHIDDEN, nullptr, 0.25f);
}

// round 17
// speedup vs baseline: 1.9369x; 1.0008x over previous
#include <cuda_runtime.h>
#include <cuda_fp16.h>
#include <math.h>
#include <stdint.h>

#define N_TOK        8192
#define DMODEL       1024
#define DQUERY       256
#define NHEADS       4
#define NSUB         128
#define TOPK         8
#define DLATENT      256
#define DHIDDEN      512
#define NEXPERTS     16384
#define NEG_INF      (-1.0e38f)

// ---------------- scratch (device globals; no allocation allowed) ----------------
__device__ float g_q[N_TOK * DMODEL];
__device__ float g_s1[N_TOK * NHEADS * NSUB];
__device__ float g_s2[N_TOK * NHEADS * NSUB];
__device__ float g_scale[DMODEL];
__device__ float g_shift[DMODEL];
__device__ float g_bnpart[16 * DMODEL];
__device__ float g_xproj[N_TOK * DHIDDEN];
__device__ float g_probs[N_TOK * NHEADS * TOPK];
__device__ int   g_eidx[N_TOK * NHEADS * TOPK];
// fp16 operand arrays
__device__ __align__(16) __half g_Hallh[NEXPERTS * DHIDDEN];   // H_all stored fp16
__device__ __align__(16) __half g_xh[N_TOK * DMODEL];
__device__ __align__(16) __half g_xl[N_TOK * DMODEL];
__device__ __align__(16) __half g_wqh[DMODEL * DMODEL];
__device__ __align__(16) __half g_wql[DMODEL * DMODEL];
__device__ __align__(16) __half g_qh[N_TOK * DMODEL];
__device__ __align__(16) __half g_ql[N_TOK * DMODEL];
__device__ __align__(16) __half g_sk1h[NSUB * 128];
__device__ __align__(16) __half g_sk1l[NSUB * 128];
__device__ __align__(16) __half g_sk2h[NSUB * 128];
__device__ __align__(16) __half g_sk2l[NSUB * 128];
__device__ __align__(16) __half g_lath[NEXPERTS * DLATENT];
__device__ __align__(16) __half g_w1th[DHIDDEN * DLATENT];
__device__ __align__(16) __half g_w2h[DHIDDEN * DMODEL];
__device__ __align__(16) __half g_wvth[DMODEL * DHIDDEN];
__device__ __align__(16) __half g_acch[N_TOK * DHIDDEN];

__device__ __forceinline__ float gelu_exact(float x) {
    return 0.5f * x * (1.0f + erff(x * 0.70710678118654752f));
}
__device__ __forceinline__ uint32_t smem_u32(const void* p) {
    uint32_t a;
    asm("{ .reg .u64 t; cvta.to.shared.u64 t, %1; cvt.u32.u64 %0, t; }" : "=r"(a) : "l"(p));
    return a;
}
__device__ __forceinline__ uint32_t sw128(uint32_t o) { return o ^ ((o >> 3) & 0x70); }

__device__ __forceinline__ void ldsm_x4(uint32_t* r, uint32_t addr) {
    asm volatile("ldmatrix.sync.aligned.m8n8.x4.shared.b16 {%0,%1,%2,%3}, [%4];"
                 : "=r"(r[0]), "=r"(r[1]), "=r"(r[2]), "=r"(r[3]) : "r"(addr));
}
__device__ __forceinline__ void mma16816h(float* d, const uint32_t* a, const uint32_t* b) {
    asm volatile(
        "mma.sync.aligned.m16n8k16.row.col.f32.f16.f16.f32 "
        "{%0,%1,%2,%3}, {%4,%5,%6,%7}, {%8,%9}, {%0,%1,%2,%3};"
        : "+f"(d[0]), "+f"(d[1]), "+f"(d[2]), "+f"(d[3])
        : "r"(a[0]), "r"(a[1]), "r"(a[2]), "r"(a[3]), "r"(b[0]), "r"(b[1]));
}

// ---------------- cp.async helpers ----------------
__device__ __forceinline__ void cp16(uint32_t dst, const void* src) {
    asm volatile("cp.async.cg.shared.global [%0], [%1], 16;"
                 :: "r"(dst), "l"(__cvta_generic_to_global(src)));
}
__device__ __forceinline__ void cp_commit() {
    asm volatile("cp.async.commit_group;" ::: "memory");
}
__device__ __forceinline__ void cp_wait0() {
    asm volatile("cp.async.wait_group 0;" ::: "memory");
}

#define TILE_BYTES 16384
#define STAGE4_BYTES (4 * TILE_BYTES)
#define GEMM4_SMEM  (2 * STAGE4_BYTES + 1024)
#define STAGE1_BYTES (2 * TILE_BYTES)
#define GEMM1_SMEM  (2 * STAGE1_BYTES + 1024)

// fp16 tile (128 rows x 64 halves = 128B/row), SW128-swizzled, via cp.async
__device__ __forceinline__ void cp_tile_h(uint32_t sm, const __half* __restrict__ src,
                                          int ld, int tid)
{
    const int row = tid >> 1;
    const int cb = (tid & 1) * 4;
    const __half* s = src + (size_t)row * ld + cb * 8;
#pragma unroll
    for (int j = 0; j < 4; j++) {
        uint32_t off = sw128((uint32_t)(row * 128 + (cb + j) * 16));
        cp16(sm + off, s + j * 8);
    }
}

// ================================================================
// fp16x3 HMMA GEMM (scoring): A,B pre-split hi/lo fp16 globals
// per-accumulator order: AhBh, AlBh, AhBl
// ================================================================
__global__ void __launch_bounds__(256, 1)
fp16_gemm(const __half* __restrict__ Ah0, const __half* __restrict__ Al0, int lda,
          const __half* __restrict__ Bh0, const __half* __restrict__ Bl0, int ldb,
          float* __restrict__ C, int ldc, int K,
          const float* __restrict__ bias)
{
    extern __shared__ char dsm[];
    const uint32_t raw = smem_u32(dsm);
    const uint32_t base = (raw + 1023) & ~1023u;

    const int tid  = threadIdx.x;
    const int lane = tid & 31;
    const int wid  = tid >> 5;
    const int wm = wid & 3;
    const int wn = wid >> 2;
    const int bm = blockIdx.y * 128;
    const int bn = blockIdx.x * 128;

    const __half* Ah = Ah0 + (size_t)bm * lda;
    const __half* Al = Al0 + (size_t)bm * lda;
    const __half* Bh = Bh0 + (size_t)bn * ldb;
    const __half* Bl = Bl0 + (size_t)bn * ldb;
    const int nk = K >> 6;

    {
        const uint32_t sb = base;
        cp_tile_h(sb,                  Ah, lda, tid);
        cp_tile_h(sb +     TILE_BYTES, Al, lda, tid);
        cp_tile_h(sb + 2 * TILE_BYTES, Bh, ldb, tid);
        cp_tile_h(sb + 3 * TILE_BYTES, Bl, ldb, tid);
        cp_commit();
        cp_wait0();
        __syncthreads();
    }

    float acc[2][8][4];
#pragma unroll
    for (int i = 0; i < 2; i++)
#pragma unroll
        for (int j = 0; j < 8; j++)
#pragma unroll
            for (int t = 0; t < 4; t++) acc[i][j][t] = 0.f;

    const int a_row = wm * 32 + (lane & 15);
    const int a_kb0 = (lane >> 4) << 4;
    const int b_row0 = wn * 64 + (lane & 7) + ((lane >> 4) << 3);
    const int b_kb0 = ((lane >> 3) & 1) << 4;

    for (int kc = 0; kc < nk; kc++) {
        const int cur = kc & 1;
        const bool more = (kc + 1 < nk);
        if (more) {
            const uint32_t sb = base + (cur ^ 1) * STAGE4_BYTES;
            cp_tile_h(sb,                  Ah + (kc + 1) * 64, lda, tid);
            cp_tile_h(sb +     TILE_BYTES, Al + (kc + 1) * 64, lda, tid);
            cp_tile_h(sb + 2 * TILE_BYTES, Bh + (kc + 1) * 64, ldb, tid);
            cp_tile_h(sb + 3 * TILE_BYTES, Bl + (kc + 1) * 64, ldb, tid);
            cp_commit();
        }
        const uint32_t sb = base + cur * STAGE4_BYTES;
#pragma unroll
        for (int ks = 0; ks < 4; ks++) {
            uint32_t Afh[2][4], Afl[2][4];
#pragma unroll
            for (int mf = 0; mf < 2; mf++) {
                uint32_t off = sw128((uint32_t)((a_row + mf * 16) * 128 + ks * 32 + a_kb0));
                ldsm_x4(Afh[mf], sb + off);
                ldsm_x4(Afl[mf], sb + TILE_BYTES + off);
            }
            uint32_t Bfh[4][4], Bfl[4][4];
#pragma unroll
            for (int nf2 = 0; nf2 < 4; nf2++) {
                uint32_t off = sw128((uint32_t)((b_row0 + nf2 * 16) * 128 + ks * 32 + b_kb0));
                ldsm_x4(Bfh[nf2], sb + 2 * TILE_BYTES + off);
                ldsm_x4(Bfl[nf2], sb + 3 * TILE_BYTES + off);
            }
#pragma unroll
            for (int nf2 = 0; nf2 < 4; nf2++)
#pragma unroll
                for (int mf = 0; mf < 2; mf++) {
                    mma16816h(acc[mf][nf2 * 2 + 0], Afh[mf], Bfh[nf2] + 0);
                    mma16816h(acc[mf][nf2 * 2 + 1], Afh[mf], Bfh[nf2] + 2);
                }
#pragma unroll
            for (int nf2 = 0; nf2 < 4; nf2++)
#pragma unroll
                for (int mf = 0; mf < 2; mf++) {
                    mma16816h(acc[mf][nf2 * 2 + 0], Afl[mf], Bfh[nf2] + 0);
                    mma16816h(acc[mf][nf2 * 2 + 1], Afl[mf], Bfh[nf2] + 2);
                }
#pragma unroll
            for (int nf2 = 0; nf2 < 4; nf2++)
#pragma unroll
                for (int mf = 0; mf < 2; mf++) {
                    mma16816h(acc[mf][nf2 * 2 + 0], Afh[mf], Bfl[nf2] + 0);
                    mma16816h(acc[mf][nf2 * 2 + 1], Afh[mf], Bfl[nf2] + 2);
                }
        }
        if (more) cp_wait0();
        __syncthreads();
    }

#pragma unroll
    for (int mf = 0; mf < 2; mf++) {
        const int row = bm + wm * 32 + mf * 16 + (lane >> 2);
#pragma unroll
        for (int nf = 0; nf < 8; nf++) {
            const int col = bn + wn * 64 + nf * 8 + (lane & 3) * 2;
            float b0 = 0.f, b1 = 0.f;
            if (bias) { b0 = bias[col]; b1 = bias[col + 1]; }
            *reinterpret_cast<float2*>(C + (size_t)row * ldc + col) =
                make_float2(acc[mf][nf][0] + b0, acc[mf][nf][1] + b1);
            *reinterpret_cast<float2*>(C + (size_t)(row + 8) * ldc + col) =
                make_float2(acc[mf][nf][2] + b0, acc[mf][nf][3] + b1);
        }
    }
}

// ================================================================
// fp16x1 HMMA GEMM (continuous): pre-rounded fp16 A,B; 2 CTAs/SM
// OH=1: write output as fp16 (for H_all)
// ================================================================
template<int ACT, int OH>
__global__ void __launch_bounds__(256, 2)
hp1_gemm(const __half* __restrict__ A0, int lda,
         const __half* __restrict__ B0, int ldb,
         float* __restrict__ C, __half* __restrict__ Ch, int ldc, int K,
         const float* __restrict__ bias, float scale)
{
    extern __shared__ char dsm[];
    const uint32_t raw = smem_u32(dsm);
    const uint32_t base = (raw + 1023) & ~1023u;

    const int tid  = threadIdx.x;
    const int lane = tid & 31;
    const int wid  = tid >> 5;
    const int wm = wid & 3;
    const int wn = wid >> 2;
    const int bm = blockIdx.y * 128;
    const int bn = blockIdx.x * 128;

    const __half* Ap = A0 + (size_t)bm * lda;
    const __half* Bp = B0 + (size_t)bn * ldb;
    const int nk = K >> 6;

    {
        const uint32_t sb = base;
        cp_tile_h(sb,              Ap, lda, tid);
        cp_tile_h(sb + TILE_BYTES, Bp, ldb, tid);
        cp_commit();
        cp_wait0();
        __syncthreads();
    }

    float acc[2][8][4];
#pragma unroll
    for (int i = 0; i < 2; i++)
#pragma unroll
        for (int j = 0; j < 8; j++)
#pragma unroll
            for (int t = 0; t < 4; t++) acc[i][j][t] = 0.f;

    const int a_row = wm * 32 + (lane & 15);
    const int a_kb0 = (lane >> 4) << 4;
    const int b_row0 = wn * 64 + (lane & 7) + ((lane >> 4) << 3);
    const int b_kb0 = ((lane >> 3) & 1) << 4;

    for (int kc = 0; kc < nk; kc++) {
        const int cur = kc & 1;
        const bool more = (kc + 1 < nk);
        if (more) {
            const uint32_t sb = base + (cur ^ 1) * STAGE1_BYTES;
            cp_tile_h(sb,              Ap + (kc + 1) * 64, lda, tid);
            cp_tile_h(sb + TILE_BYTES, Bp + (kc + 1) * 64, ldb, tid);
            cp_commit();
        }
        const uint32_t sb = base + cur * STAGE1_BYTES;
#pragma unroll
        for (int ks = 0; ks < 4; ks++) {
            uint32_t Afh[2][4];
#pragma unroll
            for (int mf = 0; mf < 2; mf++) {
                uint32_t off = sw128((uint32_t)((a_row + mf * 16) * 128 + ks * 32 + a_kb0));
                ldsm_x4(Afh[mf], sb + off);
            }
            uint32_t Bfh[4][4];
#pragma unroll
            for (int nf2 = 0; nf2 < 4; nf2++) {
                uint32_t off = sw128((uint32_t)((b_row0 + nf2 * 16) * 128 + ks * 32 + b_kb0));
                ldsm_x4(Bfh[nf2], sb + TILE_BYTES + off);
            }
#pragma unroll
            for (int nf2 = 0; nf2 < 4; nf2++)
#pragma unroll
                for (int mf = 0; mf < 2; mf++) {
                    mma16816h(acc[mf][nf2 * 2 + 0], Afh[mf], Bfh[nf2] + 0);
                    mma16816h(acc[mf][nf2 * 2 + 1], Afh[mf], Bfh[nf2] + 2);
                }
        }
        if (more) cp_wait0();
        __syncthreads();
    }

#pragma unroll
    for (int mf = 0; mf < 2; mf++) {
        const int row = bm + wm * 32 + mf * 16 + (lane >> 2);
#pragma unroll
        for (int nf = 0; nf < 8; nf++) {
            const int col = bn + wn * 64 + nf * 8 + (lane & 3) * 2;
            float b0 = 0.f, b1 = 0.f;
            if (bias) { b0 = bias[col]; b1 = bias[col + 1]; }
            float v0 = acc[mf][nf][0] + b0;
            float v1 = acc[mf][nf][1] + b1;
            float v2 = acc[mf][nf][2] + b0;
            float v3 = acc[mf][nf][3] + b1;
            if (ACT == 1) {
                v0 = gelu_exact(v0); v1 = gelu_exact(v1);
                v2 = gelu_exact(v2); v3 = gelu_exact(v3);
            }
            v0 *= scale; v1 *= scale; v2 *= scale; v3 *= scale;
            if (OH) {
                __half2 p0 = __floats2half2_rn(v0, v1);
                __half2 p1 = __floats2half2_rn(v2, v3);
                *reinterpret_cast<__half2*>(Ch + (size_t)row * ldc + col) = p0;
                *reinterpret_cast<__half2*>(Ch + (size_t)(row + 8) * ldc + col) = p1;
            } else {
                *reinterpret_cast<float2*>(C + (size_t)row * ldc + col) = make_float2(v0, v1);
                *reinterpret_cast<float2*>(C + (size_t)(row + 8) * ldc + col) = make_float2(v2, v3);
            }
        }
    }
}

// ================================================================
// operand prep kernels
// ================================================================
__device__ __forceinline__ void pack_split4(float4 v, uint2& hp, uint2& lp)
{
    __half h0 = __float2half_rn(v.x);
    __half h1 = __float2half_rn(v.y);
    __half h2 = __float2half_rn(v.z);
    __half h3 = __float2half_rn(v.w);
    __half l0 = __float2half_rn(v.x - __half2float(h0));
    __half l1 = __float2half_rn(v.y - __half2float(h1));
    __half l2 = __float2half_rn(v.z - __half2float(h2));
    __half l3 = __float2half_rn(v.w - __half2float(h3));
    hp.x = ((uint32_t)__half_as_ushort(h1) << 16) | __half_as_ushort(h0);
    hp.y = ((uint32_t)__half_as_ushort(h3) << 16) | __half_as_ushort(h2);
    lp.x = ((uint32_t)__half_as_ushort(l1) << 16) | __half_as_ushort(l0);
    lp.y = ((uint32_t)__half_as_ushort(l3) << 16) | __half_as_ushort(l2);
}
__device__ __forceinline__ uint2 pack_round4(float4 v)
{
    uint2 h;
    h.x = ((uint32_t)__half_as_ushort(__float2half_rn(v.y)) << 16)
        | __half_as_ushort(__float2half_rn(v.x));
    h.y = ((uint32_t)__half_as_ushort(__float2half_rn(v.w)) << 16)
        | __half_as_ushort(__float2half_rn(v.z));
    return h;
}

__global__ void __launch_bounds__(256)
split_fp16_kernel(const float* __restrict__ src,
                  __half* __restrict__ hi, __half* __restrict__ lo)
{
    const int i = blockIdx.x * 256 + threadIdx.x;
    float4 v = reinterpret_cast<const float4*>(src)[i];
    uint2 hp, lp;
    pack_split4(v, hp, lp);
    reinterpret_cast<uint2*>(hi)[i] = hp;
    reinterpret_cast<uint2*>(lo)[i] = lp;
}

__global__ void __launch_bounds__(256)
round_fp16_kernel(const float* __restrict__ src, __half* __restrict__ hi)
{
    const int i = blockIdx.x * 256 + threadIdx.x;
    reinterpret_cast<uint2*>(hi)[i] =
        pack_round4(reinterpret_cast<const float4*>(src)[i]);
}

__global__ void __launch_bounds__(256)
round_fp16_strided(const float* __restrict__ src, int sld, int cols4,
                   __half* __restrict__ hi)
{
    const int i = blockIdx.x * 256 + threadIdx.x;
    const int row = i / cols4, c4 = i % cols4;
    float4 v = *reinterpret_cast<const float4*>(src + (size_t)row * sld + c4 * 4);
    reinterpret_cast<uint2*>(hi)[i] = pack_round4(v);
}

__global__ void __launch_bounds__(256)
transpose_h_kernel(const float* __restrict__ src, int sld, int rows,
                   __half* __restrict__ dst)
{
    __shared__ float t[32][33];
    const int bx = blockIdx.x * 32, by = blockIdx.y * 32;
    int x = bx + threadIdx.x, y = by + threadIdx.y;
#pragma unroll
    for (int i = 0; i < 32; i += 8)
        t[threadIdx.y + i][threadIdx.x] = src[(size_t)(y + i) * sld + x];
    __syncthreads();
    x = by + threadIdx.x; y = bx + threadIdx.y;
#pragma unroll
    for (int i = 0; i < 32; i += 8)
        dst[(size_t)(y + i) * rows + x] = __float2half_rn(t[threadIdx.x][threadIdx.y + i]);
}

// ---------------- batchnorm: partial stats, then finalize ----------------
__global__ void __launch_bounds__(256)
bn_part_kernel(const float* __restrict__ q, float* __restrict__ part)
{
    const int lane32 = threadIdx.x & 31;
    const int grp = threadIdx.x >> 5;
    const int col = blockIdx.x * 32 + lane32;
    const int slice = blockIdx.y;
    const int r0 = slice * (N_TOK / 8);
    float s = 0.f, ss = 0.f;
    for (int r = grp; r < N_TOK / 8; r += 8) {
        float v = q[(size_t)(r0 + r) * DMODEL + col];
        s += v;
        ss += v * v;
    }
    __shared__ float sh_s[8][33], sh_q[8][33];
    sh_s[grp][lane32] = s;
    sh_q[grp][lane32] = ss;
    __syncthreads();
    if (grp == 0) {
        float ts = 0.f, tss = 0.f;
#pragma unroll
        for (int i = 0; i < 8; i++) { ts += sh_s[i][lane32]; tss += sh_q[i][lane32]; }
        part[(2 * slice + 0) * DMODEL + col] = ts;
        part[(2 * slice + 1) * DMODEL + col] = tss;
    }
}

__global__ void __launch_bounds__(256)
bn_final_kernel(const float* __restrict__ part,
                const float* __restrict__ gamma, const float* __restrict__ beta,
                float* __restrict__ scale, float* __restrict__ shift)
{
    const int col = blockIdx.x * 256 + threadIdx.x;
    float s = 0.f, ss = 0.f;
#pragma unroll
    for (int i = 0; i < 8; i++) {
        s  += part[(2 * i + 0) * DMODEL + col];
        ss += part[(2 * i + 1) * DMODEL + col];
    }
    float mean = s * (1.0f / N_TOK);
    float var = ss * (1.0f / N_TOK) - mean * mean;
    float rstd = rsqrtf(var + 1e-5f);
    float sc = gamma[col] * rstd;
    scale[col] = sc;
    shift[col] = beta[col] - mean * sc;
}

__global__ void __launch_bounds__(256)
normalize_split_kernel(const float* __restrict__ q,
                       const float* __restrict__ scale, const float* __restrict__ shift,
                       __half* __restrict__ qh, __half* __restrict__ ql)
{
    int i = blockIdx.x * blockDim.x + threadIdx.x;
    float4 v = reinterpret_cast<const float4*>(q)[i];
    int c = (i * 4) & (DMODEL - 1);
    v.x = v.x * scale[c + 0] + shift[c + 0];
    v.y = v.y * scale[c + 1] + shift[c + 1];
    v.z = v.z * scale[c + 2] + shift[c + 2];
    v.w = v.w * scale[c + 3] + shift[c + 3];
    uint2 hp, lp;
    pack_split4(v, hp, lp);
    reinterpret_cast<uint2*>(qh)[i] = hp;
    reinterpret_cast<uint2*>(ql)[i] = lp;
}

// ---------------- warp-collective top-16 of 128 values ----------------
__device__ __forceinline__ void warp_top16(const float* __restrict__ row,
                                           float* __restrict__ ov, int* __restrict__ oi,
                                           int lane)
{
    float v0 = row[lane], v1 = row[lane + 32], v2 = row[lane + 64], v3 = row[lane + 96];
#pragma unroll 1
    for (int it = 0; it < 16; it++) {
        float bv = v0; int bu = 0;
        if (v1 > bv) { bv = v1; bu = 1; }
        if (v2 > bv) { bv = v2; bu = 2; }
        if (v3 > bv) { bv = v3; bu = 3; }
        int bidx = lane + (bu << 5);
#pragma unroll
        for (int off = 16; off; off >>= 1) {
            float ovv = __shfl_down_sync(0xffffffffu, bv, off);
            int oii = __shfl_down_sync(0xffffffffu, bidx, off);
            if (ovv > bv) { bv = ovv; bidx = oii; }
        }
        bv = __shfl_sync(0xffffffffu, bv, 0);
        bidx = __shfl_sync(0xffffffffu, bidx, 0);
        if (lane == 0) { ov[it] = bv; oi[it] = bidx; }
        if ((bidx & 31) == lane) {
            int u = bidx >> 5;
            if (u == 0) v0 = NEG_INF;
            else if (u == 1) v1 = NEG_INF;
            else if (u == 2) v2 = NEG_INF;
            else v3 = NEG_INF;
        }
    }
}

__global__ void __launch_bounds__(256)
topk_kernel(const float* __restrict__ s1, const float* __restrict__ s2,
            float* __restrict__ probs, int* __restrict__ eidx)
{
    const int wid = threadIdx.x >> 5;
    const int lane = threadIdx.x & 31;
    const int row = blockIdx.x * 8 + wid;
    __shared__ float tv1[8][16], tv2[8][16];
    __shared__ int ti1[8][16], ti2[8][16];

    warp_top16(s1 + (size_t)row * NSUB, tv1[wid], ti1[wid], lane);
    warp_top16(s2 + (size_t)row * NSUB, tv2[wid], ti2[wid], lane);
    __syncwarp();

    float cv[8];
#pragma unroll
    for (int t = 0; t < 8; t++) {
        int c = lane * 8 + t;
        cv[t] = tv1[wid][c >> 4] + tv2[wid][c & 15];
    }
    float fv[8]; int fi[8];
#pragma unroll 1
    for (int it = 0; it < 8; it++) {
        float bv = cv[0]; int bt = 0;
#pragma unroll
        for (int t = 1; t < 8; t++) if (cv[t] > bv) { bv = cv[t]; bt = t; }
        int bidx = lane * 8 + bt;
#pragma unroll
        for (int off = 16; off; off >>= 1) {
            float ovv = __shfl_down_sync(0xffffffffu, bv, off);
            int oii = __shfl_down_sync(0xffffffffu, bidx, off);
            if (ovv > bv) { bv = ovv; bidx = oii; }
        }
        bv = __shfl_sync(0xffffffffu, bv, 0);
        bidx = __shfl_sync(0xffffffffu, bidx, 0);
        fv[it] = bv; fi[it] = bidx;
        if ((bidx >> 3) == lane) cv[bidx & 7] = NEG_INF;
    }

    if (lane < 8) {
        float m = fv[0];
        float sum = 0.f;
#pragma unroll
        for (int i = 0; i < 8; i++) sum += expf(fv[i] - m);
        float p = expf(fv[lane] - m) / sum;
        int c = fi[lane];
        int i1 = ti1[wid][c >> 4];
        int i2 = ti2[wid][c & 15];
        probs[(size_t)row * 8 + lane] = p;
        eidx[(size_t)row * 8 + lane] = i1 * NSUB + i2;
    }
}

// ---------------- MoE per-token: warp-per-expert; Hall fp16 ----------------
__global__ void __launch_bounds__(256)
moe_kernel(const float* __restrict__ xproj, const __half* __restrict__ Hall,
           const float* __restrict__ probs, const int* __restrict__ eidx,
           __half* __restrict__ acch)
{
    const int n = blockIdx.x;
    const int t = threadIdx.x;
    const int lane = t & 31, w = t >> 5;
    __shared__ float part[8][DHIDDEN];

    float xpr[16];
#pragma unroll
    for (int j = 0; j < 16; j++)
        xpr[j] = xproj[(size_t)n * DHIDDEN + j * 32 + lane];

    float pa[16];
#pragma unroll
    for (int j = 0; j < 16; j++) pa[j] = 0.f;

#pragma unroll
    for (int je = 0; je < 4; je++) {
        const int s = w * 4 + je;
        const int e = eidx[n * 32 + s];
        const __half* H = Hall + (size_t)e * DHIDDEN;
        float h[16];
#pragma unroll
        for (int j = 0; j < 16; j++) h[j] = __half2float(H[j * 32 + lane]);
        float dot = 0.f;
#pragma unroll
        for (int j = 0; j < 16; j++) dot = fmaf(xpr[j], h[j], dot);
#pragma unroll
        for (int off = 16; off; off >>= 1)
            dot += __shfl_xor_sync(0xffffffffu, dot, off);
        const float act = gelu_exact(dot) * probs[n * 32 + s];
#pragma unroll
        for (int j = 0; j < 16; j++) pa[j] = fmaf(act, h[j], pa[j]);
    }
#pragma unroll
    for (int j = 0; j < 16; j++) part[w][j * 32 + lane] = pa[j];
    __syncthreads();

    float a0 = 0.f, a1 = 0.f;
#pragma unroll
    for (int w2 = 0; w2 < 8; w2++) {
        a0 += part[w2][t];
        a1 += part[w2][t + 256];
    }
    acch[(size_t)n * DHIDDEN + t]       = __float2half_rn(a0);
    acch[(size_t)n * DHIDDEN + 256 + t] = __float2half_rn(a1);
}

// ---------------- host launch ----------------
extern "C" void kernel_launch(void* const* d_in, const int* in_sizes, int n_in,
                              void* d_out, int out_size)
{
    const float* x       = (const float*)d_in[0];
    const float* Wq      = (const float*)d_in[1];
    const float* bq      = (const float*)d_in[2];
    const float* gamma   = (const float*)d_in[3];
    const float* beta    = (const float*)d_in[4];
    const float* sk1     = (const float*)d_in[5];
    const float* sk2     = (const float*)d_in[6];
    const float* latents = (const float*)d_in[7];
    const float* W1      = (const float*)d_in[8];
    const float* W2      = (const float*)d_in[9];
    float* out = (float*)d_out;

#define SYM(var, sym) void* p_##var; cudaGetSymbolAddress(&p_##var, sym);
    SYM(q, g_q) SYM(s1, g_s1) SYM(s2, g_s2)
    SYM(sc, g_scale) SYM(sh, g_shift) SYM(bp, g_bnpart)
    SYM(Hh, g_Hallh) SYM(xp, g_xproj)
    SYM(pr, g_probs) SYM(ei, g_eidx)
    SYM(xh, g_xh) SYM(xl, g_xl)
    SYM(wqh, g_wqh) SYM(wql, g_wql)
    SYM(qh, g_qh) SYM(ql, g_ql)
    SYM(sk1h, g_sk1h) SYM(sk1l, g_sk1l) SYM(sk2h, g_sk2h) SYM(sk2l, g_sk2l)
    SYM(lath, g_lath) SYM(w1th, g_w1th) SYM(w2h, g_w2h)
    SYM(wvth, g_wvth) SYM(acch, g_acch)
#undef SYM

    cudaFuncSetAttribute(fp16_gemm, cudaFuncAttributeMaxDynamicSharedMemorySize, GEMM4_SMEM);
    cudaFuncSetAttribute((const void*)hp1_gemm<0,0>, cudaFuncAttributeMaxDynamicSharedMemorySize, GEMM1_SMEM);
    cudaFuncSetAttribute((const void*)hp1_gemm<1,1>, cudaFuncAttributeMaxDynamicSharedMemorySize, GEMM1_SMEM);

    const dim3 blk(256);
    const dim3 tblk(32, 8);

    // ---- prep (5 launches so q-GEMM is the 6th for ncu -s 5 -c 1) ----
    split_fp16_kernel<<<(N_TOK * DMODEL / 4) / 256, blk>>>(x, (__half*)p_xh, (__half*)p_xl);
    split_fp16_kernel<<<(DMODEL * DMODEL / 4) / 256, blk>>>(Wq, (__half*)p_wqh, (__half*)p_wql);
    split_fp16_kernel<<<(NSUB * 128 / 4) / 256, blk>>>(sk1, (__half*)p_sk1h, (__half*)p_sk1l);
    split_fp16_kernel<<<(NSUB * 128 / 4) / 256, blk>>>(sk2, (__half*)p_sk2h, (__half*)p_sk2l);
    round_fp16_kernel<<<(NEXPERTS * DLATENT / 4) / 256, blk>>>(latents, (__half*)p_lath);

    // 6th launch: q = x @ Wq^T + bq   (fp16x3, cp.async)
    fp16_gemm<<<dim3(DMODEL / 128, N_TOK / 128), blk, GEMM4_SMEM>>>(
        (__half*)p_xh, (__half*)p_xl, DMODEL, (__half*)p_wqh, (__half*)p_wql, DMODEL,
        (float*)p_q, DMODEL, DMODEL, bq);

    // remaining prep
    round_fp16_strided<<<(DHIDDEN * DMODEL / 4) / 256, blk>>>(W2, 2 * DMODEL, DMODEL / 4, (__half*)p_w2h);
    transpose_h_kernel<<<dim3(DHIDDEN / 32, DLATENT / 32), tblk>>>(W1, DHIDDEN, DLATENT, (__half*)p_w1th);
    transpose_h_kernel<<<dim3(DMODEL / 32, DHIDDEN / 32), tblk>>>(W2 + DMODEL, 2 * DMODEL, DHIDDEN, (__half*)p_wvth);

    // batchnorm stats
    bn_part_kernel<<<dim3(DMODEL / 32, 8), blk>>>((float*)p_q, (float*)p_bp);
    bn_final_kernel<<<DMODEL / 256, blk>>>((float*)p_bp, gamma, beta, (float*)p_sc, (float*)p_sh);

    // H_all = gelu(latents @ W1T^T)   (fp16x1, output fp16)
    hp1_gemm<1,1><<<dim3(DHIDDEN / 128, NEXPERTS / 128), blk, GEMM1_SMEM>>>(
        (__half*)p_lath, DLATENT, (__half*)p_w1th, DLATENT,
        nullptr, (__half*)p_Hh, DHIDDEN, DLATENT, nullptr, 1.0f);

    // normalize + split q -> qh/ql
    normalize_split_kernel<<<(N_TOK * DMODEL / 4) / 256, blk>>>(
        (float*)p_q, (float*)p_sc, (float*)p_sh, (__half*)p_qh, (__half*)p_ql);

    // s1/s2 (fp16x3)
    fp16_gemm<<<dim3(1, (N_TOK * NHEADS) / 128), blk, GEMM4_SMEM>>>(
        (__half*)p_qh, (__half*)p_ql, DQUERY, (__half*)p_sk1h, (__half*)p_sk1l, NSUB,
        (float*)p_s1, NSUB, NSUB, nullptr);
    fp16_gemm<<<dim3(1, (N_TOK * NHEADS) / 128), blk, GEMM4_SMEM>>>(
        (__half*)p_qh + 128, (__half*)p_ql + 128, DQUERY, (__half*)p_sk2h, (__half*)p_sk2l, NSUB,
        (float*)p_s2, NSUB, NSUB, nullptr);

    // two-level top-k
    topk_kernel<<<(N_TOK * NHEADS) / 8, blk>>>((float*)p_s1, (float*)p_s2, (float*)p_pr, (int*)p_ei);

    // x_proj = x @ W2[:, :D]^T   (fp16x1)
    hp1_gemm<0,0><<<dim3(DHIDDEN / 128, N_TOK / 128), blk, GEMM1_SMEM>>>(
        (__half*)p_xh, DMODEL, (__half*)p_w2h, DMODEL,
        (float*)p_xp, nullptr, DHIDDEN, DMODEL, nullptr, 1.0f);

    // MoE gather / act / accumulate (Hall fp16, writes acc fp16)
    moe_kernel<<<N_TOK, blk>>>((float*)p_xp, (__half*)p_Hh, (float*)p_pr, (int*)p_ei,
                               (__half*)p_acch);

    // out = acc @ WvT^T / 4   (fp16x1)
    hp1_gemm<0,0><<<dim3(DMODEL / 128, N_TOK / 128), blk, GEMM1_SMEM>>>(
        (__half*)p_acch, DHIDDEN, (__half*)p_wvth, DHIDDEN,
        out, nullptr, DMODEL, DHIDDEN, nullptr, 0.25f);
}